// round 10
// baseline (speedup 1.0000x reference)
#include <cuda_runtime.h>
#include <cuda_bf16.h>
#include <math.h>

#define HW 65536
#define Bn 2

// ---------------- scratch ----------------
__device__ float g_xp[Bn * HW];
__device__ float g_h192[Bn * 192 * HW];
__device__ float g_m192[Bn * 192 * HW];
__device__ float g_m64[Bn * 64 * HW];
__device__ double g_ps1[64][4], g_ps2[64][4];
__device__ float g_a[64], g_bc[64];
__device__ double g_ym[Bn * 64];
__device__ float g_y[Bn * 64];
// channel-last bf16 hi|lo input for mid convs: [b][px][128]
__device__ __nv_bfloat16 g_hc[(size_t)Bn * HW * 128];
// per-tap weights, rows [oc][hi 64 | lo 64] bf16 (permuted ic order)
__device__ __nv_bfloat16 g_wc3[9 * 64 * 128];
__device__ __nv_bfloat16 g_wc5[25 * 64 * 128];
__device__ __nv_bfloat16 g_wc7[49 * 64 * 128];

// permuted within-16 element index (k-pair interleave so LDS.64 = (k01,k89) frag regs)
__device__ __host__ __forceinline__ int permCol(int ic) {
    int jj = ic & 15, q = jj >> 1, e = jj & 1;
    int sp = (q < 4) ? 2 * q : 2 * (q - 4) + 1;
    return (ic & ~15) + 2 * sp + e;
}

// ---------------- preprocess ----------------
__device__ __forceinline__ float blendf(float v) {
    float g = fminf(fmaxf((v + 1.0f) * 0.5f, 1e-6f), 1.0f);
    return 0.6f * g + 0.4f * g * sqrtf(g);
}

__global__ void k_pre(const float* __restrict__ x) {
    int idx = blockIdx.x * blockDim.x + threadIdx.x;
    if (idx >= Bn * HW) return;
    int b = idx >> 16, p = idx & (HW - 1);
    int i = p >> 8, j = p & 255;
    const float* xb = x + b * HW;
    float c = blendf(xb[p]);
    const int   di[13] = {-2,-1,-1,-1, 0, 0, 0, 0, 0, 1, 1, 1, 2};
    const int   dj[13] = { 0,-1, 0, 1,-2,-1, 0, 1, 2,-1, 0, 1, 0};
    const float sw[13] = {0.99920032f,0.99960008f,0.99980002f,0.99960008f,
                          0.99920032f,0.99980002f,1.0f,0.99980002f,0.99920032f,
                          0.99960008f,0.99980002f,0.99960008f,0.99920032f};
    float num = 0.f, den = 0.f;
#pragma unroll
    for (int t = 0; t < 13; t++) {
        int ri = i + di[t]; ri = ri < 0 ? -ri : (ri > 255 ? 510 - ri : ri);
        int rj = j + dj[t]; rj = rj < 0 ? -rj : (rj > 255 ? 510 - rj : rj);
        float sh = blendf(xb[ri * 256 + rj]);
        float d = sh - c;
        float w = sw[t] * expf(-200.0f * d * d);
        num = fmaf(w, sh, num);
        den += w;
    }
    g_xp[idx] = num / den;
}

// ---------------- fused input convs: 1 -> 64 x three kernels sizes ----------------
template<int R>
__device__ __forceinline__ void conv1_body(
        float* tile, float* ws,
        const float* __restrict__ in, const float* __restrict__ w,
        float* __restrict__ out, int brBase, int ysub) {
    constexpr int K = 2 * R + 1, K2 = K * K;
    constexpr int TW = 32 + 2 * R;
    int bx = blockIdx.x;
    int tx0 = (bx & 7) * 32, ty0 = (bx >> 3) * 32;
    int b = ysub >> 3, ocg = ysub & 7;
    int oc0 = ocg * 8;
    int tid = threadIdx.x;            // 256
    const float* icp = in + (size_t)b * HW;
    for (int t = tid; t < TW * TW; t += 256) {
        int yy = ty0 - R + t / TW, xx = tx0 - R + t % TW;
        tile[t] = (yy >= 0 && yy < 256 && xx >= 0 && xx < 256)
                ? __ldg(&icp[yy * 256 + xx]) : 0.f;
    }
    for (int t = tid; t < 8 * K2; t += 256) {
        int o = t / K2;
        ws[t] = w[(size_t)(oc0 + o) * K2 + (t - o * K2)];
    }
    __syncthreads();
    int row = tid >> 3, xq = (tid & 7) * 4;
    float acc[8][4];
#pragma unroll
    for (int o = 0; o < 8; o++)
#pragma unroll
        for (int q = 0; q < 4; q++) acc[o][q] = 0.f;
#pragma unroll
    for (int ky = 0; ky < K; ky++) {
#pragma unroll
        for (int kx = 0; kx < K; kx++) {
            int base = (row + ky) * TW + xq + kx;
            float t0 = tile[base], t1 = tile[base + 1];
            float t2 = tile[base + 2], t3 = tile[base + 3];
#pragma unroll
            for (int o = 0; o < 8; o++) {
                float wv = ws[o * K2 + ky * K + kx];
                acc[o][0] = fmaf(t0, wv, acc[o][0]);
                acc[o][1] = fmaf(t1, wv, acc[o][1]);
                acc[o][2] = fmaf(t2, wv, acc[o][2]);
                acc[o][3] = fmaf(t3, wv, acc[o][3]);
            }
        }
    }
    size_t ob = (size_t)(b * 192 + brBase + oc0) * HW + (ty0 + row) * 256 + tx0 + xq;
#pragma unroll
    for (int o = 0; o < 8; o++)
#pragma unroll
        for (int q = 0; q < 4; q++)
            out[ob + (size_t)o * HW + q] = fmaxf(acc[o][q], 0.f);
}

// grid (64, 48): y>>4 selects branch (R=1/2/3), y&15 = b*8 + ocg.
__global__ void __launch_bounds__(256) k_conv1f(
        const float* __restrict__ xp,
        const float* __restrict__ w3, const float* __restrict__ w5,
        const float* __restrict__ w7, float* __restrict__ out) {
    __shared__ float tile[38 * 38];
    __shared__ float ws[8 * 49];
    int br = blockIdx.y >> 4;
    int ysub = blockIdx.y & 15;
    if (br == 0)      conv1_body<1>(tile, ws, xp, w3, out, 0,   ysub);
    else if (br == 1) conv1_body<2>(tile, ws, xp, w5, out, 64,  ysub);
    else              conv1_body<3>(tile, ws, xp, w7, out, 128, ysub);
}

// ---------------- bf16 mma helper ----------------
__device__ __forceinline__ void mma_bf16(float* d, unsigned a0, unsigned a1,
                                         unsigned a2, unsigned a3,
                                         unsigned b0, unsigned b1) {
    asm("mma.sync.aligned.m16n8k16.row.col.f32.bf16.bf16.f32 "
        "{%0,%1,%2,%3},{%4,%5,%6,%7},{%8,%9},{%0,%1,%2,%3};"
        : "+f"(d[0]), "+f"(d[1]), "+f"(d[2]), "+f"(d[3])
        : "r"(a0), "r"(a1), "r"(a2), "r"(a3), "r"(b0), "r"(b1));
}

// hi/lo split + pack two values into bf16x2 words
__device__ __forceinline__ unsigned packhl(float a, float b, unsigned& lo) {
    __nv_bfloat16 ha = __float2bfloat16_rn(a);
    __nv_bfloat16 hb = __float2bfloat16_rn(b);
    float la = a - __bfloat162float(ha);
    float lb = b - __bfloat162float(hb);
    __nv_bfloat162 l2 = __float22bfloat162_rn(make_float2(la, lb));
    lo = *reinterpret_cast<unsigned*>(&l2);
    __nv_bfloat162 h2; h2.x = ha; h2.y = hb;
    return *reinterpret_cast<unsigned*>(&h2);
}

// ---------------- planar 1x1 conv via tensor cores: 192 -> 64 ----------------
// CTA 256 thr: 256 px, all 64 oc. Warp w owns px [w*32, w*32+32).
// EPI 0: write channel-last bf16 hi|lo (g_hc format); extra grid slice
//        (blockIdx.y == Bn) performs ALL mid-conv weight conversion.
// EPI 1: planar fp32 store.
template<int EPI>
__global__ void __launch_bounds__(256) k_p1x1(
        const float* __restrict__ in, const float* __restrict__ w,
        float* __restrict__ outPlanar, __nv_bfloat16* __restrict__ outCL,
        const float* __restrict__ wb3, const float* __restrict__ wb5,
        const float* __restrict__ wb7,
        __nv_bfloat16* __restrict__ wc3, __nv_bfloat16* __restrict__ wc5,
        __nv_bfloat16* __restrict__ wc7) {
    extern __shared__ char sm[];

    // ---- weight-conversion side slice (EPI 0 only) ----
    if (EPI == 0 && blockIdx.y == Bn) {
        int gid = blockIdx.x * 256 + threadIdx.x;   // 0..65535
        for (int idx = gid; idx < 83 * 4096; idx += 65536) {
            int u = idx >> 12, r = idx & 4095;
            int oc = r >> 6, ic = r & 63;
            const float* wsrc; __nv_bfloat16* wdst; int K2, tap;
            if (u < 9)       { wsrc = wb3; wdst = wc3; K2 = 9;  tap = u; }
            else if (u < 34) { wsrc = wb5; wdst = wc5; K2 = 25; tap = u - 9; }
            else             { wsrc = wb7; wdst = wc7; K2 = 49; tap = u - 34; }
            float v = wsrc[((size_t)oc * 64 + ic) * K2 + tap];
            __nv_bfloat16 hi = __float2bfloat16_rn(v);
            float lo = v - __bfloat162float(hi);
            __nv_bfloat16* row = wdst + ((size_t)tap * 64 + oc) * 128;
            int col = permCol(ic);
            row[col] = hi;
            row[64 + col] = __float2bfloat16_rn(lo);
        }
        return;
    }

    char* wsmH = sm;
    char* wsmL = sm + 25600;
    char* bsmH = sm + 51200;
    char* bsmL = sm + 59520;

    int tid = threadIdx.x;
    int b = blockIdx.y;
    int px0 = blockIdx.x * 256;
    int warp = tid >> 5, lane = tid & 31;
    int lr = lane >> 2, lc = lane & 3;
    int kp = warp;
    int px8 = lane * 8;
    int pxw = warp * 32;

    const float* X = in + (size_t)b * 192 * HW + px0;

    // ---- load weights, split hi/lo ----
    {
        int oc = tid >> 2, seg = tid & 3;
        const float* wr = w + oc * 192 + seg * 48;
        __nv_bfloat16* dh = (__nv_bfloat16*)(wsmH + oc * 400) + seg * 48;
        __nv_bfloat16* dl = (__nv_bfloat16*)(wsmL + oc * 400) + seg * 48;
        for (int i = 0; i < 48; i++) {
            float v = __ldg(&wr[i]);
            __nv_bfloat16 h = __float2bfloat16_rn(v);
            dh[i] = h;
            dl[i] = __float2bfloat16_rn(v - __bfloat162float(h));
        }
    }
    // ---- stage chunk 0 ----
    {
        const float* r0 = X + (size_t)(2 * kp) * HW + px8;
        const float* r1 = r0 + HW;
        float4 p0 = *(const float4*)r0, p1 = *(const float4*)(r0 + 4);
        float4 p2 = *(const float4*)r1, p3 = *(const float4*)(r1 + 4);
        uint4 H0, L0, H1, L1;
        H0.x = packhl(p0.x, p2.x, L0.x); H0.y = packhl(p0.y, p2.y, L0.y);
        H0.z = packhl(p0.z, p2.z, L0.z); H0.w = packhl(p0.w, p2.w, L0.w);
        H1.x = packhl(p1.x, p3.x, L1.x); H1.y = packhl(p1.y, p3.y, L1.y);
        H1.z = packhl(p1.z, p3.z, L1.z); H1.w = packhl(p1.w, p3.w, L1.w);
        *(uint4*)(bsmH + kp * 1040 + lane * 32) = H0;
        *(uint4*)(bsmH + kp * 1040 + lane * 32 + 16) = H1;
        *(uint4*)(bsmL + kp * 1040 + lane * 32) = L0;
        *(uint4*)(bsmL + kp * 1040 + lane * 32 + 16) = L1;
    }
    __syncthreads();

    float d[4][4][4];
#pragma unroll
    for (int mf = 0; mf < 4; mf++)
#pragma unroll
        for (int nf = 0; nf < 4; nf++)
#pragma unroll
            for (int q = 0; q < 4; q++) d[mf][nf][q] = 0.f;

    for (int c = 0; c < 12; c++) {
        float4 p0, p1, p2, p3;
        bool more = (c < 11);
        if (more) {
            const float* r0 = X + (size_t)((c + 1) * 16 + 2 * kp) * HW + px8;
            const float* r1 = r0 + HW;
            p0 = *(const float4*)r0; p1 = *(const float4*)(r0 + 4);
            p2 = *(const float4*)r1; p3 = *(const float4*)(r1 + 4);
        }
        unsigned BH0[4], BH1[4], BL0[4], BL1[4];
#pragma unroll
        for (int nf = 0; nf < 4; nf++) {
            int col = (pxw + nf * 8 + lr) * 4;
            const char* ph = bsmH + lc * 1040 + col;
            const char* pl = bsmL + lc * 1040 + col;
            BH0[nf] = *(const unsigned*)ph;
            BH1[nf] = *(const unsigned*)(ph + 4 * 1040);
            BL0[nf] = *(const unsigned*)pl;
            BL1[nf] = *(const unsigned*)(pl + 4 * 1040);
        }
#pragma unroll
        for (int mf = 0; mf < 4; mf++) {
            const char* ah = wsmH + (mf * 16 + lr) * 400 + c * 32 + lc * 4;
            const char* al = wsmL + (mf * 16 + lr) * 400 + c * 32 + lc * 4;
            unsigned AH0 = *(const unsigned*)ah;
            unsigned AH1 = *(const unsigned*)(ah + 8 * 400);
            unsigned AH2 = *(const unsigned*)(ah + 16);
            unsigned AH3 = *(const unsigned*)(ah + 8 * 400 + 16);
            unsigned AL0 = *(const unsigned*)al;
            unsigned AL1 = *(const unsigned*)(al + 8 * 400);
            unsigned AL2 = *(const unsigned*)(al + 16);
            unsigned AL3 = *(const unsigned*)(al + 8 * 400 + 16);
#pragma unroll
            for (int nf = 0; nf < 4; nf++) {
                mma_bf16(d[mf][nf], AH0, AH1, AH2, AH3, BH0[nf], BH1[nf]);
                mma_bf16(d[mf][nf], AH0, AH1, AH2, AH3, BL0[nf], BL1[nf]);
                mma_bf16(d[mf][nf], AL0, AL1, AL2, AL3, BH0[nf], BH1[nf]);
            }
        }
        __syncthreads();
        if (more) {
            uint4 H0, L0, H1, L1;
            H0.x = packhl(p0.x, p2.x, L0.x); H0.y = packhl(p0.y, p2.y, L0.y);
            H0.z = packhl(p0.z, p2.z, L0.z); H0.w = packhl(p0.w, p2.w, L0.w);
            H1.x = packhl(p1.x, p3.x, L1.x); H1.y = packhl(p1.y, p3.y, L1.y);
            H1.z = packhl(p1.z, p3.z, L1.z); H1.w = packhl(p1.w, p3.w, L1.w);
            *(uint4*)(bsmH + kp * 1040 + lane * 32) = H0;
            *(uint4*)(bsmH + kp * 1040 + lane * 32 + 16) = H1;
            *(uint4*)(bsmL + kp * 1040 + lane * 32) = L0;
            *(uint4*)(bsmL + kp * 1040 + lane * 32 + 16) = L1;
        }
        __syncthreads();
    }

    if (EPI == 1) {
#pragma unroll
        for (int mf = 0; mf < 4; mf++) {
            int oc = mf * 16 + lr;
#pragma unroll
            for (int nf = 0; nf < 4; nf++) {
                int px = px0 + pxw + nf * 8 + 2 * lc;
                *(float2*)&outPlanar[(size_t)(b * 64 + oc) * HW + px] =
                    make_float2(d[mf][nf][0], d[mf][nf][1]);
                *(float2*)&outPlanar[(size_t)(b * 64 + oc + 8) * HW + px] =
                    make_float2(d[mf][nf][2], d[mf][nf][3]);
            }
        }
    } else {
        char* est = sm + warp * 8704;   // [32 px][272 B rows, 16B-aligned]
#pragma unroll
        for (int mf = 0; mf < 4; mf++) {
            int col0 = permCol(mf * 16 + lr);
            int col8 = permCol(mf * 16 + lr + 8);
#pragma unroll
            for (int nf = 0; nf < 4; nf++) {
                int pxl = nf * 8 + 2 * lc;
#pragma unroll
                for (int e = 0; e < 2; e++) {
                    {
                        float v = d[mf][nf][e];
                        __nv_bfloat16 h = __float2bfloat16_rn(v);
                        *(__nv_bfloat16*)(est + (pxl + e) * 272 + col0 * 2) = h;
                        *(__nv_bfloat16*)(est + (pxl + e) * 272 + (64 + col0) * 2) =
                            __float2bfloat16_rn(v - __bfloat162float(h));
                    }
                    {
                        float v = d[mf][nf][2 + e];
                        __nv_bfloat16 h = __float2bfloat16_rn(v);
                        *(__nv_bfloat16*)(est + (pxl + e) * 272 + col8 * 2) = h;
                        *(__nv_bfloat16*)(est + (pxl + e) * 272 + (64 + col8) * 2) =
                            __float2bfloat16_rn(v - __bfloat162float(h));
                    }
                }
            }
        }
        __syncthreads();
#pragma unroll
        for (int r = 0; r < 16; r++) {
            int pxl = r * 2 + (lane >> 4);
            int ch = lane & 15;
            uint4 v = *(const uint4*)(sm + warp * 8704 + pxl * 272 + ch * 16);
            *(uint4*)((char*)outCL + ((size_t)b * HW + px0 + pxw + pxl) * 256 + ch * 16) = v;
        }
    }
}

// ---------------- mid conv: 64->64, KxK, tensor-core bf16 hi/lo ----------------
template<int R>
__global__ void __launch_bounds__(256) k_mconv(
        const __nv_bfloat16* __restrict__ wc,
        float* __restrict__ out, int brBase) {
    constexpr int K = 2 * R + 1, K2 = K * K;
    constexpr int TWX = 32 + 2 * R, TWY = 8 + 2 * R, ROWS = TWX * TWY;
    constexpr int RB = 272;
    constexpr int WB1 = 64 * 272;
    extern __shared__ char smem[];
    char* tile = smem;
    char* wbuf = smem + ROWS * RB;

    int tid = threadIdx.x;
    int b = blockIdx.z;
    int x0 = blockIdx.x * 32, y0 = blockIdx.y * 8;
    int warp = tid >> 5, lane = tid & 31;
    int wm = warp >> 1, wn = warp & 1;
    int lr = lane >> 2, lc = lane & 3;

    {
        const __nv_bfloat16* src = g_hc + (size_t)b * HW * 128;
        for (int r0 = 0; r0 < ROWS; r0 += 16) {
            int row = r0 + (tid >> 4);
            if (row < ROWS) {
                int gy = y0 - R + row / TWX;
                int gx = x0 - R + row % TWX;
                uint4 v = make_uint4(0u, 0u, 0u, 0u);
                if (gy >= 0 && gy < 256 && gx >= 0 && gx < 256)
                    v = *(const uint4*)(src + ((size_t)gy * 256 + gx) * 128 + (tid & 15) * 8);
                *(uint4*)(tile + row * RB + (tid & 15) * 16) = v;
            }
        }
    }
    {
        const uint4* src = (const uint4*)wc;
        int o = tid * 64, row = o >> 8, col = o & 255;
#pragma unroll
        for (int i = 0; i < 4; i++) {
            uint4 v = src[tid * 4 + i];
            *(uint4*)(wbuf + row * RB + col + i * 16) = v;
        }
    }
    __syncthreads();

    float d[4][4][4];
#pragma unroll
    for (int f = 0; f < 4; f++)
#pragma unroll
        for (int n = 0; n < 4; n++)
#pragma unroll
            for (int q = 0; q < 4; q++) d[f][n][q] = 0.f;

    for (int tap = 0; tap < K2; tap++) {
        int cur = tap & 1, nxt = cur ^ 1;
        uint4 pv[4];
        bool more = (tap + 1 < K2);
        if (more) {
            const uint4* src = (const uint4*)(wc + (size_t)(tap + 1) * 64 * 128);
#pragma unroll
            for (int i = 0; i < 4; i++) pv[i] = src[tid * 4 + i];
        }
        int ky = tap / K, kx = tap % K;
        const char* wb = wbuf + cur * WB1;
        int abase[4];
#pragma unroll
        for (int f = 0; f < 4; f++)
            abase[f] = (((wm * 2 + (f >> 1) + ky) * TWX) + ((f & 1) * 16) + lr + kx) * RB + lc * 8;

#pragma unroll
        for (int c = 0; c < 4; c++) {
            int co = c * 32;
            uint2 AH0[4], AH1[4], AL0[4], AL1[4];
#pragma unroll
            for (int f = 0; f < 4; f++) {
                const char* p = tile + abase[f] + co;
                AH0[f] = *(const uint2*)p;
                AH1[f] = *(const uint2*)(p + 8 * RB);
                AL0[f] = *(const uint2*)(p + 128);
                AL1[f] = *(const uint2*)(p + 128 + 8 * RB);
            }
            uint2 BH[4], BL[4];
#pragma unroll
            for (int n = 0; n < 4; n++) {
                const char* p = wb + (wn * 32 + n * 8 + lr) * RB + co + lc * 8;
                BH[n] = *(const uint2*)p;
                BL[n] = *(const uint2*)(p + 128);
            }
#pragma unroll
            for (int f = 0; f < 4; f++)
#pragma unroll
                for (int n = 0; n < 4; n++) {
                    mma_bf16(d[f][n], AH0[f].x, AH1[f].x, AH0[f].y, AH1[f].y, BH[n].x, BH[n].y);
                    mma_bf16(d[f][n], AH0[f].x, AH1[f].x, AH0[f].y, AH1[f].y, BL[n].x, BL[n].y);
                    mma_bf16(d[f][n], AL0[f].x, AL1[f].x, AL0[f].y, AL1[f].y, BH[n].x, BH[n].y);
                }
        }
        if (more) {
            int o = tid * 64, row = o >> 8, col = o & 255;
#pragma unroll
            for (int i = 0; i < 4; i++)
                *(uint4*)(wbuf + nxt * WB1 + row * RB + col + i * 16) = pv[i];
        }
        __syncthreads();
    }

#pragma unroll
    for (int f = 0; f < 4; f++) {
        int y = y0 + wm * 2 + (f >> 1);
        int x = x0 + (f & 1) * 16 + lr;
#pragma unroll
        for (int n = 0; n < 4; n++) {
            int oc = wn * 32 + n * 8 + lc * 2;
            float* o0 = out + ((size_t)(b * 192 + brBase + oc) * HW + y * 256 + x);
            o0[0]       = fmaxf(d[f][n][0], 0.f);
            o0[8]       = fmaxf(d[f][n][2], 0.f);
            o0[HW]      = fmaxf(d[f][n][1], 0.f);
            o0[HW + 8]  = fmaxf(d[f][n][3], 0.f);
        }
    }
}

// ---------------- BN stats ----------------
__global__ void k_bnsum() {
    int c = blockIdx.x >> 2, seg = blockIdx.x & 3, tid = threadIdx.x;
    int base = seg * 32768;
    double s[4] = {0, 0, 0, 0}, s2[4] = {0, 0, 0, 0};
    for (int u = 0; u < 32; u++) {
        int t = base + u * 1024 + tid * 4;
#pragma unroll
        for (int q = 0; q < 4; q++) {
            int tt = t + q;
            int bb = tt >> 16, p = tt & (HW - 1);
            float v = g_m64[(size_t)(bb * 64 + c) * HW + p];
            s[q] += v; s2[q] += (double)v * v;
        }
    }
    double ss = (s[0] + s[1]) + (s[2] + s[3]);
    double ss2 = (s2[0] + s2[1]) + (s2[2] + s2[3]);
    __shared__ double sh1[256], sh2[256];
    sh1[tid] = ss; sh2[tid] = ss2; __syncthreads();
    for (int st = 128; st > 0; st >>= 1) {
        if (tid < st) { sh1[tid] += sh1[tid + st]; sh2[tid] += sh2[tid + st]; }
        __syncthreads();
    }
    if (tid == 0) { g_ps1[c][seg] = sh1[0]; g_ps2[c][seg] = sh2[0]; }
}

__global__ void k_bncoef(const float* __restrict__ bn_g, const float* __restrict__ bn_b) {
    int c = threadIdx.x;
    double N = (double)(Bn * HW);
    double s1 = (g_ps1[c][0] + g_ps1[c][1]) + (g_ps1[c][2] + g_ps1[c][3]);
    double s2 = (g_ps2[c][0] + g_ps2[c][1]) + (g_ps2[c][2] + g_ps2[c][3]);
    double mean = s1 / N;
    double var = s2 / N - mean * mean;
    float a = (float)((double)bn_g[c] / sqrt(var + 1e-5));
    g_a[c] = a;
    g_bc[c] = bn_b[c] - (float)mean * a;
}

__global__ void k_ymean() {
    int c = blockIdx.x, b = blockIdx.y, tid = threadIdx.x;
    float a = g_a[c], bc = g_bc[c];
    const float* mp = g_m64 + (size_t)(b * 64 + c) * HW;
    double s[4] = {0, 0, 0, 0};
    for (int p = tid * 4; p < HW; p += 1024) {
#pragma unroll
        for (int q = 0; q < 4; q++)
            s[q] += (double)fmaxf(fmaf(a, mp[p + q], bc), 0.f);
    }
    __shared__ double sh[256];
    sh[tid] = (s[0] + s[1]) + (s[2] + s[3]); __syncthreads();
    for (int st = 128; st > 0; st >>= 1) {
        if (tid < st) sh[tid] += sh[tid + st];
        __syncthreads();
    }
    if (tid == 0) g_ym[b * 64 + c] = sh[0] / (double)HW;
}

__global__ void k_se(const float* __restrict__ se1, const float* __restrict__ se2) {
    __shared__ float t1[2][4];
    int tid = threadIdx.x;
    for (int b = 0; b < 2; b++) {
        if (tid < 4) {
            float s = 0.f;
            for (int c = 0; c < 64; c++) s += se1[tid * 64 + c] * (float)g_ym[b * 64 + c];
            t1[b][tid] = fmaxf(s, 0.f);
        }
    }
    __syncthreads();
    for (int b = 0; b < 2; b++) {
        float z = 0.f;
        for (int j = 0; j < 4; j++) z += se2[tid * 4 + j] * t1[b][j];
        g_y[b * 64 + tid] = 1.f / (1.f + expf(-z));
    }
}

// ---------------- final: interior fast path + 3 accumulators ----------------
__global__ void k_final(const float* __restrict__ wf, float* __restrict__ out) {
    __shared__ float wy[576], sa[64], sb[64];
    int b = blockIdx.y;
    int tid = threadIdx.x;
    for (int t = tid; t < 576; t += 256) {
        int c = t / 9;
        wy[t] = __ldg(&wf[t]) * g_y[b * 64 + c];
    }
    if (tid < 64) { sa[tid] = g_a[tid]; sb[tid] = g_bc[tid]; }
    __syncthreads();
    int bx = blockIdx.x;
    int tx0 = (bx & 15) * 16, ty0 = (bx >> 4) * 16;
    int i = ty0 + (tid >> 4), j = tx0 + (tid & 15);
    const float* mb = g_m64 + (size_t)b * 64 * HW;
    float a0 = 0.f, a1 = 0.f, a2 = 0.f;
    bool interior = (tx0 > 0) && (tx0 < 240) && (ty0 > 0) && (ty0 < 240);
    if (interior) {
        const float* p0 = mb + (i - 1) * 256 + (j - 1);
        for (int c = 0; c < 64; c++) {
            float a = sa[c], bc = sb[c];
            const float* pc = p0 + (size_t)c * HW;
            const float* wt = wy + c * 9;
            float r;
            r = fmaxf(fmaf(a, __ldg(&pc[0]),   bc), 0.f); a0 = fmaf(wt[0], r, a0);
            r = fmaxf(fmaf(a, __ldg(&pc[1]),   bc), 0.f); a1 = fmaf(wt[1], r, a1);
            r = fmaxf(fmaf(a, __ldg(&pc[2]),   bc), 0.f); a2 = fmaf(wt[2], r, a2);
            r = fmaxf(fmaf(a, __ldg(&pc[256]), bc), 0.f); a0 = fmaf(wt[3], r, a0);
            r = fmaxf(fmaf(a, __ldg(&pc[257]), bc), 0.f); a1 = fmaf(wt[4], r, a1);
            r = fmaxf(fmaf(a, __ldg(&pc[258]), bc), 0.f); a2 = fmaf(wt[5], r, a2);
            r = fmaxf(fmaf(a, __ldg(&pc[512]), bc), 0.f); a0 = fmaf(wt[6], r, a0);
            r = fmaxf(fmaf(a, __ldg(&pc[513]), bc), 0.f); a1 = fmaf(wt[7], r, a1);
            r = fmaxf(fmaf(a, __ldg(&pc[514]), bc), 0.f); a2 = fmaf(wt[8], r, a2);
        }
    } else {
        for (int c = 0; c < 64; c++) {
            float a = sa[c], bc = sb[c];
            const float* mc = mb + (size_t)c * HW;
#pragma unroll
            for (int ky = 0; ky < 3; ky++) {
                int yy = i + ky - 1; if (yy < 0 || yy > 255) continue;
#pragma unroll
                for (int kx = 0; kx < 3; kx++) {
                    int xx = j + kx - 1; if (xx < 0 || xx > 255) continue;
                    float v = __ldg(&mc[yy * 256 + xx]);
                    float r = fmaxf(fmaf(a, v, bc), 0.f);
                    a0 = fmaf(wy[c * 9 + ky * 3 + kx], r, a0);
                }
            }
        }
    }
    int p = i * 256 + j;
    out[b * HW + p] = g_xp[b * HW + p] - ((a0 + a1) + a2);
}

// ---------------- launch ----------------
extern "C" void kernel_launch(void* const* d_in, const int* in_sizes, int n_in,
                              void* d_out, int out_size) {
    const float* x    = (const float*)d_in[0];
    const float* w_i3 = (const float*)d_in[1];
    const float* w_i5 = (const float*)d_in[2];
    const float* w_i7 = (const float*)d_in[3];
    const float* w_p1 = (const float*)d_in[4];
    const float* wb3  = (const float*)d_in[5];
    const float* wb5  = (const float*)d_in[6];
    const float* wb7  = (const float*)d_in[7];
    const float* wbp  = (const float*)d_in[8];
    const float* bn_g = (const float*)d_in[9];
    const float* bn_b = (const float*)d_in[10];
    const float* se1  = (const float*)d_in[11];
    const float* se2  = (const float*)d_in[12];
    const float* wf   = (const float*)d_in[13];
    float* out = (float*)d_out;

    float *xp, *h192, *m192, *m64;
    cudaGetSymbolAddress((void**)&xp,   g_xp);
    cudaGetSymbolAddress((void**)&h192, g_h192);
    cudaGetSymbolAddress((void**)&m192, g_m192);
    cudaGetSymbolAddress((void**)&m64,  g_m64);
    __nv_bfloat16 *hc, *wc3, *wc5, *wc7;
    cudaGetSymbolAddress((void**)&hc,  g_hc);
    cudaGetSymbolAddress((void**)&wc3, g_wc3);
    cudaGetSymbolAddress((void**)&wc5, g_wc5);
    cudaGetSymbolAddress((void**)&wc7, g_wc7);

    const int smem1 = (34 * 10) * 272 + 2 * 64 * 272;
    const int smem2 = (36 * 12) * 272 + 2 * 64 * 272;
    const int smem3 = (38 * 14) * 272 + 2 * 64 * 272;
    const int smemP = 8 * 8704;
    cudaFuncSetAttribute(k_mconv<1>, cudaFuncAttributeMaxDynamicSharedMemorySize, smem1);
    cudaFuncSetAttribute(k_mconv<2>, cudaFuncAttributeMaxDynamicSharedMemorySize, smem2);
    cudaFuncSetAttribute(k_mconv<3>, cudaFuncAttributeMaxDynamicSharedMemorySize, smem3);
    cudaFuncSetAttribute(k_p1x1<0>, cudaFuncAttributeMaxDynamicSharedMemorySize, smemP);
    cudaFuncSetAttribute(k_p1x1<1>, cudaFuncAttributeMaxDynamicSharedMemorySize, smemP);

    // Launch order tuned so ncu (-s 5 -c 1, two harness launches ahead)
    // captures k_mconv<3> (my index 3).
    k_pre<<<512, 256>>>(x);                                                 // 0
    k_conv1f<<<dim3(64, 48), 256>>>(xp, w_i3, w_i5, w_i7, h192);            // 1
    k_p1x1<0><<<dim3(256, Bn + 1), 256, smemP>>>(h192, w_p1, nullptr, hc,
                                                 wb3, wb5, wb7,
                                                 wc3, wc5, wc7);            // 2
    dim3 gm(8, 32, Bn);
    k_mconv<3><<<gm, 256, smem3>>>(wc7, m192, 128);                         // 3 (profiled)
    k_mconv<1><<<gm, 256, smem1>>>(wc3, m192, 0);                           // 4
    k_mconv<2><<<gm, 256, smem2>>>(wc5, m192, 64);                          // 5
    k_p1x1<1><<<dim3(256, Bn), 256, smemP>>>(m192, wbp, m64, nullptr,
                                             nullptr, nullptr, nullptr,
                                             nullptr, nullptr, nullptr);    // 6
    k_bnsum<<<256, 256>>>();                                                // 7
    k_bncoef<<<1, 64>>>(bn_g, bn_b);                                        // 8
    k_ymean<<<dim3(64, 2), 256>>>();                                        // 9
    k_se<<<1, 64>>>(se1, se2);                                              // 10
    k_final<<<dim3(256, 2), 256>>>(wf, out);                                // 11
}

// round 11
// speedup vs baseline: 1.0557x; 1.0557x over previous
#include <cuda_runtime.h>
#include <cuda_bf16.h>
#include <math.h>

#define HW 65536
#define Bn 2

// ---------------- scratch ----------------
__device__ float g_xp[Bn * HW];
__device__ float g_h192[Bn * 192 * HW];
__device__ float g_m192[Bn * 192 * HW];
__device__ float g_m64[Bn * 64 * HW];
__device__ double g_ps1[64][4], g_ps2[64][4];
__device__ float g_a[64], g_bc[64];
__device__ double g_ym[Bn * 64];
__device__ float g_y[Bn * 64];
// channel-last bf16 hi|lo input for mid convs: [b][px][128]
__device__ __nv_bfloat16 g_hc[(size_t)Bn * HW * 128];
// per-tap weights, rows [oc][hi 64 | lo 64] bf16 (permuted ic order)
__device__ __nv_bfloat16 g_wc3[9 * 64 * 128];
__device__ __nv_bfloat16 g_wc5[25 * 64 * 128];
__device__ __nv_bfloat16 g_wc7[49 * 64 * 128];

// permuted within-16 element index (k-pair interleave so LDS.64 = (k01,k89) frag regs)
__device__ __host__ __forceinline__ int permCol(int ic) {
    int jj = ic & 15, q = jj >> 1, e = jj & 1;
    int sp = (q < 4) ? 2 * q : 2 * (q - 4) + 1;
    return (ic & ~15) + 2 * sp + e;
}

// ---------------- preprocess ----------------
__device__ __forceinline__ float blendf(float v) {
    float g = fminf(fmaxf((v + 1.0f) * 0.5f, 1e-6f), 1.0f);
    return 0.6f * g + 0.4f * g * sqrtf(g);
}

__global__ void k_pre(const float* __restrict__ x) {
    int idx = blockIdx.x * blockDim.x + threadIdx.x;
    if (idx >= Bn * HW) return;
    int b = idx >> 16, p = idx & (HW - 1);
    int i = p >> 8, j = p & 255;
    const float* xb = x + b * HW;
    float c = blendf(xb[p]);
    const int   di[13] = {-2,-1,-1,-1, 0, 0, 0, 0, 0, 1, 1, 1, 2};
    const int   dj[13] = { 0,-1, 0, 1,-2,-1, 0, 1, 2,-1, 0, 1, 0};
    const float sw[13] = {0.99920032f,0.99960008f,0.99980002f,0.99960008f,
                          0.99920032f,0.99980002f,1.0f,0.99980002f,0.99920032f,
                          0.99960008f,0.99980002f,0.99960008f,0.99920032f};
    float num = 0.f, den = 0.f;
#pragma unroll
    for (int t = 0; t < 13; t++) {
        int ri = i + di[t]; ri = ri < 0 ? -ri : (ri > 255 ? 510 - ri : ri);
        int rj = j + dj[t]; rj = rj < 0 ? -rj : (rj > 255 ? 510 - rj : rj);
        float sh = blendf(xb[ri * 256 + rj]);
        float d = sh - c;
        float w = sw[t] * expf(-200.0f * d * d);
        num = fmaf(w, sh, num);
        den += w;
    }
    g_xp[idx] = num / den;
}

// ---------------- fused input convs: 1 -> 64 x three kernel sizes ----------------
template<int R>
__device__ __forceinline__ void conv1_body(
        float* tile, float* ws,
        const float* __restrict__ in, const float* __restrict__ w,
        float* __restrict__ out, int brBase, int ysub) {
    constexpr int K = 2 * R + 1, K2 = K * K;
    constexpr int TW = 32 + 2 * R;
    int bx = blockIdx.x;
    int tx0 = (bx & 7) * 32, ty0 = (bx >> 3) * 32;
    int b = ysub >> 3, ocg = ysub & 7;
    int oc0 = ocg * 8;
    int tid = threadIdx.x;            // 256
    const float* icp = in + (size_t)b * HW;
    for (int t = tid; t < TW * TW; t += 256) {
        int yy = ty0 - R + t / TW, xx = tx0 - R + t % TW;
        tile[t] = (yy >= 0 && yy < 256 && xx >= 0 && xx < 256)
                ? __ldg(&icp[yy * 256 + xx]) : 0.f;
    }
    for (int t = tid; t < 8 * K2; t += 256) {
        int o = t / K2;
        ws[t] = w[(size_t)(oc0 + o) * K2 + (t - o * K2)];
    }
    __syncthreads();
    int row = tid >> 3, xq = (tid & 7) * 4;
    float acc[8][4];
#pragma unroll
    for (int o = 0; o < 8; o++)
#pragma unroll
        for (int q = 0; q < 4; q++) acc[o][q] = 0.f;
#pragma unroll
    for (int ky = 0; ky < K; ky++) {
#pragma unroll
        for (int kx = 0; kx < K; kx++) {
            int base = (row + ky) * TW + xq + kx;
            float t0 = tile[base], t1 = tile[base + 1];
            float t2 = tile[base + 2], t3 = tile[base + 3];
#pragma unroll
            for (int o = 0; o < 8; o++) {
                float wv = ws[o * K2 + ky * K + kx];
                acc[o][0] = fmaf(t0, wv, acc[o][0]);
                acc[o][1] = fmaf(t1, wv, acc[o][1]);
                acc[o][2] = fmaf(t2, wv, acc[o][2]);
                acc[o][3] = fmaf(t3, wv, acc[o][3]);
            }
        }
    }
    size_t ob = (size_t)(b * 192 + brBase + oc0) * HW + (ty0 + row) * 256 + tx0 + xq;
#pragma unroll
    for (int o = 0; o < 8; o++)
#pragma unroll
        for (int q = 0; q < 4; q++)
            out[ob + (size_t)o * HW + q] = fmaxf(acc[o][q], 0.f);
}

// grid (64, 48): y>>4 selects branch (R=1/2/3), y&15 = b*8 + ocg.
__global__ void __launch_bounds__(256) k_conv1f(
        const float* __restrict__ xp,
        const float* __restrict__ w3, const float* __restrict__ w5,
        const float* __restrict__ w7, float* __restrict__ out) {
    __shared__ float tile[38 * 38];
    __shared__ float ws[8 * 49];
    int br = blockIdx.y >> 4;
    int ysub = blockIdx.y & 15;
    if (br == 0)      conv1_body<1>(tile, ws, xp, w3, out, 0,   ysub);
    else if (br == 1) conv1_body<2>(tile, ws, xp, w5, out, 64,  ysub);
    else              conv1_body<3>(tile, ws, xp, w7, out, 128, ysub);
}

// ---------------- bf16 mma helper ----------------
__device__ __forceinline__ void mma_bf16(float* d, unsigned a0, unsigned a1,
                                         unsigned a2, unsigned a3,
                                         unsigned b0, unsigned b1) {
    asm("mma.sync.aligned.m16n8k16.row.col.f32.bf16.bf16.f32 "
        "{%0,%1,%2,%3},{%4,%5,%6,%7},{%8,%9},{%0,%1,%2,%3};"
        : "+f"(d[0]), "+f"(d[1]), "+f"(d[2]), "+f"(d[3])
        : "r"(a0), "r"(a1), "r"(a2), "r"(a3), "r"(b0), "r"(b1));
}

// hi/lo split + pack two values into bf16x2 words
__device__ __forceinline__ unsigned packhl(float a, float b, unsigned& lo) {
    __nv_bfloat16 ha = __float2bfloat16_rn(a);
    __nv_bfloat16 hb = __float2bfloat16_rn(b);
    float la = a - __bfloat162float(ha);
    float lb = b - __bfloat162float(hb);
    __nv_bfloat162 l2 = __float22bfloat162_rn(make_float2(la, lb));
    lo = *reinterpret_cast<unsigned*>(&l2);
    __nv_bfloat162 h2; h2.x = ha; h2.y = hb;
    return *reinterpret_cast<unsigned*>(&h2);
}

// ---------------- planar 1x1 conv via tensor cores: 192 -> 64 ----------------
// EPI 0: write channel-last bf16 hi|lo (g_hc format); extra grid slice
//        (blockIdx.y == Bn) performs ALL mid-conv weight conversion.
// EPI 1: planar fp32 store.
template<int EPI>
__global__ void __launch_bounds__(256) k_p1x1(
        const float* __restrict__ in, const float* __restrict__ w,
        float* __restrict__ outPlanar, __nv_bfloat16* __restrict__ outCL,
        const float* __restrict__ wb3, const float* __restrict__ wb5,
        const float* __restrict__ wb7,
        __nv_bfloat16* __restrict__ wc3, __nv_bfloat16* __restrict__ wc5,
        __nv_bfloat16* __restrict__ wc7) {
    extern __shared__ char sm[];

    // ---- weight-conversion side slice (EPI 0 only) ----
    if (EPI == 0 && blockIdx.y == Bn) {
        int gid = blockIdx.x * 256 + threadIdx.x;   // 0..65535
        for (int idx = gid; idx < 83 * 4096; idx += 65536) {
            int u = idx >> 12, r = idx & 4095;
            int oc = r >> 6, ic = r & 63;
            const float* wsrc; __nv_bfloat16* wdst; int K2, tap;
            if (u < 9)       { wsrc = wb3; wdst = wc3; K2 = 9;  tap = u; }
            else if (u < 34) { wsrc = wb5; wdst = wc5; K2 = 25; tap = u - 9; }
            else             { wsrc = wb7; wdst = wc7; K2 = 49; tap = u - 34; }
            float v = wsrc[((size_t)oc * 64 + ic) * K2 + tap];
            __nv_bfloat16 hi = __float2bfloat16_rn(v);
            float lo = v - __bfloat162float(hi);
            __nv_bfloat16* row = wdst + ((size_t)tap * 64 + oc) * 128;
            int col = permCol(ic);
            row[col] = hi;
            row[64 + col] = __float2bfloat16_rn(lo);
        }
        return;
    }

    char* wsmH = sm;
    char* wsmL = sm + 25600;
    char* bsmH = sm + 51200;
    char* bsmL = sm + 59520;

    int tid = threadIdx.x;
    int b = blockIdx.y;
    int px0 = blockIdx.x * 256;
    int warp = tid >> 5, lane = tid & 31;
    int lr = lane >> 2, lc = lane & 3;
    int kp = warp;
    int px8 = lane * 8;
    int pxw = warp * 32;

    const float* X = in + (size_t)b * 192 * HW + px0;

    // ---- load weights, split hi/lo ----
    {
        int oc = tid >> 2, seg = tid & 3;
        const float* wr = w + oc * 192 + seg * 48;
        __nv_bfloat16* dh = (__nv_bfloat16*)(wsmH + oc * 400) + seg * 48;
        __nv_bfloat16* dl = (__nv_bfloat16*)(wsmL + oc * 400) + seg * 48;
        for (int i = 0; i < 48; i++) {
            float v = __ldg(&wr[i]);
            __nv_bfloat16 h = __float2bfloat16_rn(v);
            dh[i] = h;
            dl[i] = __float2bfloat16_rn(v - __bfloat162float(h));
        }
    }
    // ---- stage chunk 0 ----
    {
        const float* r0 = X + (size_t)(2 * kp) * HW + px8;
        const float* r1 = r0 + HW;
        float4 p0 = *(const float4*)r0, p1 = *(const float4*)(r0 + 4);
        float4 p2 = *(const float4*)r1, p3 = *(const float4*)(r1 + 4);
        uint4 H0, L0, H1, L1;
        H0.x = packhl(p0.x, p2.x, L0.x); H0.y = packhl(p0.y, p2.y, L0.y);
        H0.z = packhl(p0.z, p2.z, L0.z); H0.w = packhl(p0.w, p2.w, L0.w);
        H1.x = packhl(p1.x, p3.x, L1.x); H1.y = packhl(p1.y, p3.y, L1.y);
        H1.z = packhl(p1.z, p3.z, L1.z); H1.w = packhl(p1.w, p3.w, L1.w);
        *(uint4*)(bsmH + kp * 1040 + lane * 32) = H0;
        *(uint4*)(bsmH + kp * 1040 + lane * 32 + 16) = H1;
        *(uint4*)(bsmL + kp * 1040 + lane * 32) = L0;
        *(uint4*)(bsmL + kp * 1040 + lane * 32 + 16) = L1;
    }
    __syncthreads();

    float d[4][4][4];
#pragma unroll
    for (int mf = 0; mf < 4; mf++)
#pragma unroll
        for (int nf = 0; nf < 4; nf++)
#pragma unroll
            for (int q = 0; q < 4; q++) d[mf][nf][q] = 0.f;

    for (int c = 0; c < 12; c++) {
        float4 p0, p1, p2, p3;
        bool more = (c < 11);
        if (more) {
            const float* r0 = X + (size_t)((c + 1) * 16 + 2 * kp) * HW + px8;
            const float* r1 = r0 + HW;
            p0 = *(const float4*)r0; p1 = *(const float4*)(r0 + 4);
            p2 = *(const float4*)r1; p3 = *(const float4*)(r1 + 4);
        }
        unsigned BH0[4], BH1[4], BL0[4], BL1[4];
#pragma unroll
        for (int nf = 0; nf < 4; nf++) {
            int col = (pxw + nf * 8 + lr) * 4;
            const char* ph = bsmH + lc * 1040 + col;
            const char* pl = bsmL + lc * 1040 + col;
            BH0[nf] = *(const unsigned*)ph;
            BH1[nf] = *(const unsigned*)(ph + 4 * 1040);
            BL0[nf] = *(const unsigned*)pl;
            BL1[nf] = *(const unsigned*)(pl + 4 * 1040);
        }
#pragma unroll
        for (int mf = 0; mf < 4; mf++) {
            const char* ah = wsmH + (mf * 16 + lr) * 400 + c * 32 + lc * 4;
            const char* al = wsmL + (mf * 16 + lr) * 400 + c * 32 + lc * 4;
            unsigned AH0 = *(const unsigned*)ah;
            unsigned AH1 = *(const unsigned*)(ah + 8 * 400);
            unsigned AH2 = *(const unsigned*)(ah + 16);
            unsigned AH3 = *(const unsigned*)(ah + 8 * 400 + 16);
            unsigned AL0 = *(const unsigned*)al;
            unsigned AL1 = *(const unsigned*)(al + 8 * 400);
            unsigned AL2 = *(const unsigned*)(al + 16);
            unsigned AL3 = *(const unsigned*)(al + 8 * 400 + 16);
#pragma unroll
            for (int nf = 0; nf < 4; nf++) {
                mma_bf16(d[mf][nf], AH0, AH1, AH2, AH3, BH0[nf], BH1[nf]);
                mma_bf16(d[mf][nf], AH0, AH1, AH2, AH3, BL0[nf], BL1[nf]);
                mma_bf16(d[mf][nf], AL0, AL1, AL2, AL3, BH0[nf], BH1[nf]);
            }
        }
        __syncthreads();
        if (more) {
            uint4 H0, L0, H1, L1;
            H0.x = packhl(p0.x, p2.x, L0.x); H0.y = packhl(p0.y, p2.y, L0.y);
            H0.z = packhl(p0.z, p2.z, L0.z); H0.w = packhl(p0.w, p2.w, L0.w);
            H1.x = packhl(p1.x, p3.x, L1.x); H1.y = packhl(p1.y, p3.y, L1.y);
            H1.z = packhl(p1.z, p3.z, L1.z); H1.w = packhl(p1.w, p3.w, L1.w);
            *(uint4*)(bsmH + kp * 1040 + lane * 32) = H0;
            *(uint4*)(bsmH + kp * 1040 + lane * 32 + 16) = H1;
            *(uint4*)(bsmL + kp * 1040 + lane * 32) = L0;
            *(uint4*)(bsmL + kp * 1040 + lane * 32 + 16) = L1;
        }
        __syncthreads();
    }

    if (EPI == 1) {
#pragma unroll
        for (int mf = 0; mf < 4; mf++) {
            int oc = mf * 16 + lr;
#pragma unroll
            for (int nf = 0; nf < 4; nf++) {
                int px = px0 + pxw + nf * 8 + 2 * lc;
                *(float2*)&outPlanar[(size_t)(b * 64 + oc) * HW + px] =
                    make_float2(d[mf][nf][0], d[mf][nf][1]);
                *(float2*)&outPlanar[(size_t)(b * 64 + oc + 8) * HW + px] =
                    make_float2(d[mf][nf][2], d[mf][nf][3]);
            }
        }
    } else {
        char* est = sm + warp * 8704;   // [32 px][272 B rows, 16B-aligned]
#pragma unroll
        for (int mf = 0; mf < 4; mf++) {
            int col0 = permCol(mf * 16 + lr);
            int col8 = permCol(mf * 16 + lr + 8);
#pragma unroll
            for (int nf = 0; nf < 4; nf++) {
                int pxl = nf * 8 + 2 * lc;
#pragma unroll
                for (int e = 0; e < 2; e++) {
                    {
                        float v = d[mf][nf][e];
                        __nv_bfloat16 h = __float2bfloat16_rn(v);
                        *(__nv_bfloat16*)(est + (pxl + e) * 272 + col0 * 2) = h;
                        *(__nv_bfloat16*)(est + (pxl + e) * 272 + (64 + col0) * 2) =
                            __float2bfloat16_rn(v - __bfloat162float(h));
                    }
                    {
                        float v = d[mf][nf][2 + e];
                        __nv_bfloat16 h = __float2bfloat16_rn(v);
                        *(__nv_bfloat16*)(est + (pxl + e) * 272 + col8 * 2) = h;
                        *(__nv_bfloat16*)(est + (pxl + e) * 272 + (64 + col8) * 2) =
                            __float2bfloat16_rn(v - __bfloat162float(h));
                    }
                }
            }
        }
        __syncthreads();
#pragma unroll
        for (int r = 0; r < 16; r++) {
            int pxl = r * 2 + (lane >> 4);
            int ch = lane & 15;
            uint4 v = *(const uint4*)(sm + warp * 8704 + pxl * 272 + ch * 16);
            *(uint4*)((char*)outCL + ((size_t)b * HW + px0 + pxw + pxl) * 256 + ch * 16) = v;
        }
    }
}

// ---------------- mid conv: 64->64, KxK, tensor-core bf16 hi/lo ----------------
// Barrier-free tap loop: input tile in smem (loaded once), weights streamed
// per-fragment from gmem (hot in L1/L2, shared by all 512 CTAs).
template<int R>
__global__ void __launch_bounds__(256) k_mconv(
        const __nv_bfloat16* __restrict__ wc,
        float* __restrict__ out, int brBase) {
    constexpr int K = 2 * R + 1, K2 = K * K;
    constexpr int TWX = 32 + 2 * R, TWY = 8 + 2 * R, ROWS = TWX * TWY;
    constexpr int RB = 272;
    extern __shared__ char smem[];
    char* tile = smem;

    int tid = threadIdx.x;
    int b = blockIdx.z;
    int x0 = blockIdx.x * 32, y0 = blockIdx.y * 8;
    int warp = tid >> 5, lane = tid & 31;
    int wm = warp >> 1, wn = warp & 1;
    int lr = lane >> 2, lc = lane & 3;

    {
        const __nv_bfloat16* src = g_hc + (size_t)b * HW * 128;
        for (int r0 = 0; r0 < ROWS; r0 += 16) {
            int row = r0 + (tid >> 4);
            if (row < ROWS) {
                int gy = y0 - R + row / TWX;
                int gx = x0 - R + row % TWX;
                uint4 v = make_uint4(0u, 0u, 0u, 0u);
                if (gy >= 0 && gy < 256 && gx >= 0 && gx < 256)
                    v = *(const uint4*)(src + ((size_t)gy * 256 + gx) * 128 + (tid & 15) * 8);
                *(uint4*)(tile + row * RB + (tid & 15) * 16) = v;
            }
        }
    }
    __syncthreads();   // only barrier in the whole kernel body

    float d[4][4][4];
#pragma unroll
    for (int f = 0; f < 4; f++)
#pragma unroll
        for (int n = 0; n < 4; n++)
#pragma unroll
            for (int q = 0; q < 4; q++) d[f][n][q] = 0.f;

    for (int tap = 0; tap < K2; tap++) {
        int ky = tap / K, kx = tap % K;
        // per-warp weight base for this tap (gmem, 256 B per oc row)
        const char* wt = (const char*)(wc + (size_t)tap * 64 * 128)
                       + (wn * 32 + lr) * 256 + lc * 8;
        int abase[4];
#pragma unroll
        for (int f = 0; f < 4; f++)
            abase[f] = (((wm * 2 + (f >> 1) + ky) * TWX) + ((f & 1) * 16) + lr + kx) * RB + lc * 8;

#pragma unroll
        for (int c = 0; c < 4; c++) {
            int co = c * 32;
            // B fragments straight from gmem (L1-hot)
            uint2 BH[4], BL[4];
#pragma unroll
            for (int n = 0; n < 4; n++) {
                const char* p = wt + n * 8 * 256 + co;
                BH[n] = __ldg((const uint2*)p);
                BL[n] = __ldg((const uint2*)(p + 128));
            }
            // A fragments from smem tile
            uint2 AH0[4], AH1[4], AL0[4], AL1[4];
#pragma unroll
            for (int f = 0; f < 4; f++) {
                const char* p = tile + abase[f] + co;
                AH0[f] = *(const uint2*)p;
                AH1[f] = *(const uint2*)(p + 8 * RB);
                AL0[f] = *(const uint2*)(p + 128);
                AL1[f] = *(const uint2*)(p + 128 + 8 * RB);
            }
#pragma unroll
            for (int f = 0; f < 4; f++)
#pragma unroll
                for (int n = 0; n < 4; n++) {
                    mma_bf16(d[f][n], AH0[f].x, AH1[f].x, AH0[f].y, AH1[f].y, BH[n].x, BH[n].y);
                    mma_bf16(d[f][n], AH0[f].x, AH1[f].x, AH0[f].y, AH1[f].y, BL[n].x, BL[n].y);
                    mma_bf16(d[f][n], AL0[f].x, AL1[f].x, AL0[f].y, AL1[f].y, BH[n].x, BH[n].y);
                }
        }
    }

#pragma unroll
    for (int f = 0; f < 4; f++) {
        int y = y0 + wm * 2 + (f >> 1);
        int x = x0 + (f & 1) * 16 + lr;
#pragma unroll
        for (int n = 0; n < 4; n++) {
            int oc = wn * 32 + n * 8 + lc * 2;
            float* o0 = out + ((size_t)(b * 192 + brBase + oc) * HW + y * 256 + x);
            o0[0]       = fmaxf(d[f][n][0], 0.f);
            o0[8]       = fmaxf(d[f][n][2], 0.f);
            o0[HW]      = fmaxf(d[f][n][1], 0.f);
            o0[HW + 8]  = fmaxf(d[f][n][3], 0.f);
        }
    }
}

// ---------------- BN stats ----------------
__global__ void k_bnsum() {
    int c = blockIdx.x >> 2, seg = blockIdx.x & 3, tid = threadIdx.x;
    int base = seg * 32768;
    double s[4] = {0, 0, 0, 0}, s2[4] = {0, 0, 0, 0};
    for (int u = 0; u < 32; u++) {
        int t = base + u * 1024 + tid * 4;
#pragma unroll
        for (int q = 0; q < 4; q++) {
            int tt = t + q;
            int bb = tt >> 16, p = tt & (HW - 1);
            float v = g_m64[(size_t)(bb * 64 + c) * HW + p];
            s[q] += v; s2[q] += (double)v * v;
        }
    }
    double ss = (s[0] + s[1]) + (s[2] + s[3]);
    double ss2 = (s2[0] + s2[1]) + (s2[2] + s2[3]);
    __shared__ double sh1[256], sh2[256];
    sh1[tid] = ss; sh2[tid] = ss2; __syncthreads();
    for (int st = 128; st > 0; st >>= 1) {
        if (tid < st) { sh1[tid] += sh1[tid + st]; sh2[tid] += sh2[tid + st]; }
        __syncthreads();
    }
    if (tid == 0) { g_ps1[c][seg] = sh1[0]; g_ps2[c][seg] = sh2[0]; }
}

__global__ void k_bncoef(const float* __restrict__ bn_g, const float* __restrict__ bn_b) {
    int c = threadIdx.x;
    double N = (double)(Bn * HW);
    double s1 = (g_ps1[c][0] + g_ps1[c][1]) + (g_ps1[c][2] + g_ps1[c][3]);
    double s2 = (g_ps2[c][0] + g_ps2[c][1]) + (g_ps2[c][2] + g_ps2[c][3]);
    double mean = s1 / N;
    double var = s2 / N - mean * mean;
    float a = (float)((double)bn_g[c] / sqrt(var + 1e-5));
    g_a[c] = a;
    g_bc[c] = bn_b[c] - (float)mean * a;
}

__global__ void k_ymean() {
    int c = blockIdx.x, b = blockIdx.y, tid = threadIdx.x;
    float a = g_a[c], bc = g_bc[c];
    const float* mp = g_m64 + (size_t)(b * 64 + c) * HW;
    double s[4] = {0, 0, 0, 0};
    for (int p = tid * 4; p < HW; p += 1024) {
#pragma unroll
        for (int q = 0; q < 4; q++)
            s[q] += (double)fmaxf(fmaf(a, mp[p + q], bc), 0.f);
    }
    __shared__ double sh[256];
    sh[tid] = (s[0] + s[1]) + (s[2] + s[3]); __syncthreads();
    for (int st = 128; st > 0; st >>= 1) {
        if (tid < st) sh[tid] += sh[tid + st];
        __syncthreads();
    }
    if (tid == 0) g_ym[b * 64 + c] = sh[0] / (double)HW;
}

__global__ void k_se(const float* __restrict__ se1, const float* __restrict__ se2) {
    __shared__ float t1[2][4];
    int tid = threadIdx.x;
    for (int b = 0; b < 2; b++) {
        if (tid < 4) {
            float s = 0.f;
            for (int c = 0; c < 64; c++) s += se1[tid * 64 + c] * (float)g_ym[b * 64 + c];
            t1[b][tid] = fmaxf(s, 0.f);
        }
    }
    __syncthreads();
    for (int b = 0; b < 2; b++) {
        float z = 0.f;
        for (int j = 0; j < 4; j++) z += se2[tid * 4 + j] * t1[b][j];
        g_y[b * 64 + tid] = 1.f / (1.f + expf(-z));
    }
}

// ---------------- final: interior fast path + 3 accumulators ----------------
__global__ void k_final(const float* __restrict__ wf, float* __restrict__ out) {
    __shared__ float wy[576], sa[64], sb[64];
    int b = blockIdx.y;
    int tid = threadIdx.x;
    for (int t = tid; t < 576; t += 256) {
        int c = t / 9;
        wy[t] = __ldg(&wf[t]) * g_y[b * 64 + c];
    }
    if (tid < 64) { sa[tid] = g_a[tid]; sb[tid] = g_bc[tid]; }
    __syncthreads();
    int bx = blockIdx.x;
    int tx0 = (bx & 15) * 16, ty0 = (bx >> 4) * 16;
    int i = ty0 + (tid >> 4), j = tx0 + (tid & 15);
    const float* mb = g_m64 + (size_t)b * 64 * HW;
    float a0 = 0.f, a1 = 0.f, a2 = 0.f;
    bool interior = (tx0 > 0) && (tx0 < 240) && (ty0 > 0) && (ty0 < 240);
    if (interior) {
        const float* p0 = mb + (i - 1) * 256 + (j - 1);
        for (int c = 0; c < 64; c++) {
            float a = sa[c], bc = sb[c];
            const float* pc = p0 + (size_t)c * HW;
            const float* wt = wy + c * 9;
            float r;
            r = fmaxf(fmaf(a, __ldg(&pc[0]),   bc), 0.f); a0 = fmaf(wt[0], r, a0);
            r = fmaxf(fmaf(a, __ldg(&pc[1]),   bc), 0.f); a1 = fmaf(wt[1], r, a1);
            r = fmaxf(fmaf(a, __ldg(&pc[2]),   bc), 0.f); a2 = fmaf(wt[2], r, a2);
            r = fmaxf(fmaf(a, __ldg(&pc[256]), bc), 0.f); a0 = fmaf(wt[3], r, a0);
            r = fmaxf(fmaf(a, __ldg(&pc[257]), bc), 0.f); a1 = fmaf(wt[4], r, a1);
            r = fmaxf(fmaf(a, __ldg(&pc[258]), bc), 0.f); a2 = fmaf(wt[5], r, a2);
            r = fmaxf(fmaf(a, __ldg(&pc[512]), bc), 0.f); a0 = fmaf(wt[6], r, a0);
            r = fmaxf(fmaf(a, __ldg(&pc[513]), bc), 0.f); a1 = fmaf(wt[7], r, a1);
            r = fmaxf(fmaf(a, __ldg(&pc[514]), bc), 0.f); a2 = fmaf(wt[8], r, a2);
        }
    } else {
        for (int c = 0; c < 64; c++) {
            float a = sa[c], bc = sb[c];
            const float* mc = mb + (size_t)c * HW;
#pragma unroll
            for (int ky = 0; ky < 3; ky++) {
                int yy = i + ky - 1; if (yy < 0 || yy > 255) continue;
#pragma unroll
                for (int kx = 0; kx < 3; kx++) {
                    int xx = j + kx - 1; if (xx < 0 || xx > 255) continue;
                    float v = __ldg(&mc[yy * 256 + xx]);
                    float r = fmaxf(fmaf(a, v, bc), 0.f);
                    a0 = fmaf(wy[c * 9 + ky * 3 + kx], r, a0);
                }
            }
        }
    }
    int p = i * 256 + j;
    out[b * HW + p] = g_xp[b * HW + p] - ((a0 + a1) + a2);
}

// ---------------- launch ----------------
extern "C" void kernel_launch(void* const* d_in, const int* in_sizes, int n_in,
                              void* d_out, int out_size) {
    const float* x    = (const float*)d_in[0];
    const float* w_i3 = (const float*)d_in[1];
    const float* w_i5 = (const float*)d_in[2];
    const float* w_i7 = (const float*)d_in[3];
    const float* w_p1 = (const float*)d_in[4];
    const float* wb3  = (const float*)d_in[5];
    const float* wb5  = (const float*)d_in[6];
    const float* wb7  = (const float*)d_in[7];
    const float* wbp  = (const float*)d_in[8];
    const float* bn_g = (const float*)d_in[9];
    const float* bn_b = (const float*)d_in[10];
    const float* se1  = (const float*)d_in[11];
    const float* se2  = (const float*)d_in[12];
    const float* wf   = (const float*)d_in[13];
    float* out = (float*)d_out;

    float *xp, *h192, *m192, *m64;
    cudaGetSymbolAddress((void**)&xp,   g_xp);
    cudaGetSymbolAddress((void**)&h192, g_h192);
    cudaGetSymbolAddress((void**)&m192, g_m192);
    cudaGetSymbolAddress((void**)&m64,  g_m64);
    __nv_bfloat16 *hc, *wc3, *wc5, *wc7;
    cudaGetSymbolAddress((void**)&hc,  g_hc);
    cudaGetSymbolAddress((void**)&wc3, g_wc3);
    cudaGetSymbolAddress((void**)&wc5, g_wc5);
    cudaGetSymbolAddress((void**)&wc7, g_wc7);

    const int smem1 = (34 * 10) * 272;   // tile only — weights stream from gmem
    const int smem2 = (36 * 12) * 272;
    const int smem3 = (38 * 14) * 272;
    const int smemP = 8 * 8704;
    cudaFuncSetAttribute(k_mconv<1>, cudaFuncAttributeMaxDynamicSharedMemorySize, smem1);
    cudaFuncSetAttribute(k_mconv<2>, cudaFuncAttributeMaxDynamicSharedMemorySize, smem2);
    cudaFuncSetAttribute(k_mconv<3>, cudaFuncAttributeMaxDynamicSharedMemorySize, smem3);
    cudaFuncSetAttribute(k_p1x1<0>, cudaFuncAttributeMaxDynamicSharedMemorySize, smemP);
    cudaFuncSetAttribute(k_p1x1<1>, cudaFuncAttributeMaxDynamicSharedMemorySize, smemP);

    // Launch order keeps k_mconv<3> at my-index 3 (ncu captures it).
    k_pre<<<512, 256>>>(x);                                                 // 0
    k_conv1f<<<dim3(64, 48), 256>>>(xp, w_i3, w_i5, w_i7, h192);            // 1
    k_p1x1<0><<<dim3(256, Bn + 1), 256, smemP>>>(h192, w_p1, nullptr, hc,
                                                 wb3, wb5, wb7,
                                                 wc3, wc5, wc7);            // 2
    dim3 gm(8, 32, Bn);
    k_mconv<3><<<gm, 256, smem3>>>(wc7, m192, 128);                         // 3 (profiled)
    k_mconv<1><<<gm, 256, smem1>>>(wc3, m192, 0);                           // 4
    k_mconv<2><<<gm, 256, smem2>>>(wc5, m192, 64);                          // 5
    k_p1x1<1><<<dim3(256, Bn), 256, smemP>>>(m192, wbp, m64, nullptr,
                                             nullptr, nullptr, nullptr,
                                             nullptr, nullptr, nullptr);    // 6
    k_bnsum<<<256, 256>>>();                                                // 7
    k_bncoef<<<1, 64>>>(bn_g, bn_b);                                        // 8
    k_ymean<<<dim3(64, 2), 256>>>();                                        // 9
    k_se<<<1, 64>>>(se1, se2);                                              // 10
    k_final<<<dim3(256, 2), 256>>>(wf, out);                                // 11
}

// round 12
// speedup vs baseline: 1.1305x; 1.0709x over previous
#include <cuda_runtime.h>
#include <cuda_bf16.h>
#include <math.h>

#define HW 65536
#define Bn 2

// ---------------- scratch ----------------
__device__ float g_xp[Bn * HW];
__device__ float g_h192[Bn * 192 * HW];
__device__ float g_m192[Bn * 192 * HW];
__device__ float g_m64[Bn * 64 * HW];
__device__ double g_ps1[64][4], g_ps2[64][4];
__device__ float g_a[64], g_bc[64];
__device__ double g_ym[Bn * 64];
__device__ float g_y[Bn * 64];
// channel-last bf16 hi|lo input for mid convs: [b][px][128]
__device__ __nv_bfloat16 g_hc[(size_t)Bn * HW * 128];
// per-tap weights, rows [oc][hi 64 | lo 64] bf16 (permuted ic order)
__device__ __nv_bfloat16 g_wc3[9 * 64 * 128];
__device__ __nv_bfloat16 g_wc5[25 * 64 * 128];
__device__ __nv_bfloat16 g_wc7[49 * 64 * 128];

// permuted within-16 element index (k-pair interleave so LDS.64 = (k01,k89) frag regs)
__device__ __host__ __forceinline__ int permCol(int ic) {
    int jj = ic & 15, q = jj >> 1, e = jj & 1;
    int sp = (q < 4) ? 2 * q : 2 * (q - 4) + 1;
    return (ic & ~15) + 2 * sp + e;
}

// ---------------- preprocess ----------------
__device__ __forceinline__ float blendf(float v) {
    float g = fminf(fmaxf((v + 1.0f) * 0.5f, 1e-6f), 1.0f);
    return 0.6f * g + 0.4f * g * sqrtf(g);
}

__global__ void k_pre(const float* __restrict__ x) {
    int idx = blockIdx.x * blockDim.x + threadIdx.x;
    if (idx >= Bn * HW) return;
    int b = idx >> 16, p = idx & (HW - 1);
    int i = p >> 8, j = p & 255;
    const float* xb = x + b * HW;
    float c = blendf(xb[p]);
    const int   di[13] = {-2,-1,-1,-1, 0, 0, 0, 0, 0, 1, 1, 1, 2};
    const int   dj[13] = { 0,-1, 0, 1,-2,-1, 0, 1, 2,-1, 0, 1, 0};
    const float sw[13] = {0.99920032f,0.99960008f,0.99980002f,0.99960008f,
                          0.99920032f,0.99980002f,1.0f,0.99980002f,0.99920032f,
                          0.99960008f,0.99980002f,0.99960008f,0.99920032f};
    float num = 0.f, den = 0.f;
#pragma unroll
    for (int t = 0; t < 13; t++) {
        int ri = i + di[t]; ri = ri < 0 ? -ri : (ri > 255 ? 510 - ri : ri);
        int rj = j + dj[t]; rj = rj < 0 ? -rj : (rj > 255 ? 510 - rj : rj);
        float sh = blendf(xb[ri * 256 + rj]);
        float d = sh - c;
        float w = sw[t] * expf(-200.0f * d * d);
        num = fmaf(w, sh, num);
        den += w;
    }
    g_xp[idx] = num / den;
}

// ---------------- fused input convs: 1 -> 64 x three kernel sizes ----------------
template<int R>
__device__ __forceinline__ void conv1_body(
        float* tile, float* ws,
        const float* __restrict__ in, const float* __restrict__ w,
        float* __restrict__ out, int brBase, int ysub) {
    constexpr int K = 2 * R + 1, K2 = K * K;
    constexpr int TW = 32 + 2 * R;
    int bx = blockIdx.x;
    int tx0 = (bx & 7) * 32, ty0 = (bx >> 3) * 32;
    int b = ysub >> 3, ocg = ysub & 7;
    int oc0 = ocg * 8;
    int tid = threadIdx.x;            // 256
    const float* icp = in + (size_t)b * HW;
    for (int t = tid; t < TW * TW; t += 256) {
        int yy = ty0 - R + t / TW, xx = tx0 - R + t % TW;
        tile[t] = (yy >= 0 && yy < 256 && xx >= 0 && xx < 256)
                ? __ldg(&icp[yy * 256 + xx]) : 0.f;
    }
    for (int t = tid; t < 8 * K2; t += 256) {
        int o = t / K2;
        ws[t] = w[(size_t)(oc0 + o) * K2 + (t - o * K2)];
    }
    __syncthreads();
    int row = tid >> 3, xq = (tid & 7) * 4;
    float acc[8][4];
#pragma unroll
    for (int o = 0; o < 8; o++)
#pragma unroll
        for (int q = 0; q < 4; q++) acc[o][q] = 0.f;
#pragma unroll
    for (int ky = 0; ky < K; ky++) {
#pragma unroll
        for (int kx = 0; kx < K; kx++) {
            int base = (row + ky) * TW + xq + kx;
            float t0 = tile[base], t1 = tile[base + 1];
            float t2 = tile[base + 2], t3 = tile[base + 3];
#pragma unroll
            for (int o = 0; o < 8; o++) {
                float wv = ws[o * K2 + ky * K + kx];
                acc[o][0] = fmaf(t0, wv, acc[o][0]);
                acc[o][1] = fmaf(t1, wv, acc[o][1]);
                acc[o][2] = fmaf(t2, wv, acc[o][2]);
                acc[o][3] = fmaf(t3, wv, acc[o][3]);
            }
        }
    }
    size_t ob = (size_t)(b * 192 + brBase + oc0) * HW + (ty0 + row) * 256 + tx0 + xq;
#pragma unroll
    for (int o = 0; o < 8; o++)
#pragma unroll
        for (int q = 0; q < 4; q++)
            out[ob + (size_t)o * HW + q] = fmaxf(acc[o][q], 0.f);
}

// grid (64, 48): y>>4 selects branch (R=1/2/3), y&15 = b*8 + ocg.
__global__ void __launch_bounds__(256) k_conv1f(
        const float* __restrict__ xp,
        const float* __restrict__ w3, const float* __restrict__ w5,
        const float* __restrict__ w7, float* __restrict__ out) {
    __shared__ float tile[38 * 38];
    __shared__ float ws[8 * 49];
    int br = blockIdx.y >> 4;
    int ysub = blockIdx.y & 15;
    if (br == 0)      conv1_body<1>(tile, ws, xp, w3, out, 0,   ysub);
    else if (br == 1) conv1_body<2>(tile, ws, xp, w5, out, 64,  ysub);
    else              conv1_body<3>(tile, ws, xp, w7, out, 128, ysub);
}

// ---------------- bf16 mma helper ----------------
__device__ __forceinline__ void mma_bf16(float* d, unsigned a0, unsigned a1,
                                         unsigned a2, unsigned a3,
                                         unsigned b0, unsigned b1) {
    asm("mma.sync.aligned.m16n8k16.row.col.f32.bf16.bf16.f32 "
        "{%0,%1,%2,%3},{%4,%5,%6,%7},{%8,%9},{%0,%1,%2,%3};"
        : "+f"(d[0]), "+f"(d[1]), "+f"(d[2]), "+f"(d[3])
        : "r"(a0), "r"(a1), "r"(a2), "r"(a3), "r"(b0), "r"(b1));
}

// hi/lo split + pack two values into bf16x2 words
__device__ __forceinline__ unsigned packhl(float a, float b, unsigned& lo) {
    __nv_bfloat16 ha = __float2bfloat16_rn(a);
    __nv_bfloat16 hb = __float2bfloat16_rn(b);
    float la = a - __bfloat162float(ha);
    float lb = b - __bfloat162float(hb);
    __nv_bfloat162 l2 = __float22bfloat162_rn(make_float2(la, lb));
    lo = *reinterpret_cast<unsigned*>(&l2);
    __nv_bfloat162 h2; h2.x = ha; h2.y = hb;
    return *reinterpret_cast<unsigned*>(&h2);
}

// ---------------- planar 1x1 conv via tensor cores: 192 -> 64 ----------------
// EPI 0: write channel-last bf16 hi|lo (g_hc format); extra grid slice
//        (blockIdx.y == Bn) performs ALL mid-conv weight conversion.
// EPI 1: planar fp32 store.
template<int EPI>
__global__ void __launch_bounds__(256) k_p1x1(
        const float* __restrict__ in, const float* __restrict__ w,
        float* __restrict__ outPlanar, __nv_bfloat16* __restrict__ outCL,
        const float* __restrict__ wb3, const float* __restrict__ wb5,
        const float* __restrict__ wb7,
        __nv_bfloat16* __restrict__ wc3, __nv_bfloat16* __restrict__ wc5,
        __nv_bfloat16* __restrict__ wc7) {
    extern __shared__ char sm[];

    // ---- weight-conversion side slice (EPI 0 only) ----
    if (EPI == 0 && blockIdx.y == Bn) {
        int gid = blockIdx.x * 256 + threadIdx.x;   // 0..65535
        for (int idx = gid; idx < 83 * 4096; idx += 65536) {
            int u = idx >> 12, r = idx & 4095;
            int oc = r >> 6, ic = r & 63;
            const float* wsrc; __nv_bfloat16* wdst; int K2, tap;
            if (u < 9)       { wsrc = wb3; wdst = wc3; K2 = 9;  tap = u; }
            else if (u < 34) { wsrc = wb5; wdst = wc5; K2 = 25; tap = u - 9; }
            else             { wsrc = wb7; wdst = wc7; K2 = 49; tap = u - 34; }
            float v = wsrc[((size_t)oc * 64 + ic) * K2 + tap];
            __nv_bfloat16 hi = __float2bfloat16_rn(v);
            float lo = v - __bfloat162float(hi);
            __nv_bfloat16* row = wdst + ((size_t)tap * 64 + oc) * 128;
            int col = permCol(ic);
            row[col] = hi;
            row[64 + col] = __float2bfloat16_rn(lo);
        }
        return;
    }

    char* wsmH = sm;
    char* wsmL = sm + 25600;
    char* bsmH = sm + 51200;
    char* bsmL = sm + 59520;

    int tid = threadIdx.x;
    int b = blockIdx.y;
    int px0 = blockIdx.x * 256;
    int warp = tid >> 5, lane = tid & 31;
    int lr = lane >> 2, lc = lane & 3;
    int kp = warp;
    int px8 = lane * 8;
    int pxw = warp * 32;

    const float* X = in + (size_t)b * 192 * HW + px0;

    // ---- load weights, split hi/lo ----
    {
        int oc = tid >> 2, seg = tid & 3;
        const float* wr = w + oc * 192 + seg * 48;
        __nv_bfloat16* dh = (__nv_bfloat16*)(wsmH + oc * 400) + seg * 48;
        __nv_bfloat16* dl = (__nv_bfloat16*)(wsmL + oc * 400) + seg * 48;
        for (int i = 0; i < 48; i++) {
            float v = __ldg(&wr[i]);
            __nv_bfloat16 h = __float2bfloat16_rn(v);
            dh[i] = h;
            dl[i] = __float2bfloat16_rn(v - __bfloat162float(h));
        }
    }
    // ---- stage chunk 0 ----
    {
        const float* r0 = X + (size_t)(2 * kp) * HW + px8;
        const float* r1 = r0 + HW;
        float4 p0 = *(const float4*)r0, p1 = *(const float4*)(r0 + 4);
        float4 p2 = *(const float4*)r1, p3 = *(const float4*)(r1 + 4);
        uint4 H0, L0, H1, L1;
        H0.x = packhl(p0.x, p2.x, L0.x); H0.y = packhl(p0.y, p2.y, L0.y);
        H0.z = packhl(p0.z, p2.z, L0.z); H0.w = packhl(p0.w, p2.w, L0.w);
        H1.x = packhl(p1.x, p3.x, L1.x); H1.y = packhl(p1.y, p3.y, L1.y);
        H1.z = packhl(p1.z, p3.z, L1.z); H1.w = packhl(p1.w, p3.w, L1.w);
        *(uint4*)(bsmH + kp * 1040 + lane * 32) = H0;
        *(uint4*)(bsmH + kp * 1040 + lane * 32 + 16) = H1;
        *(uint4*)(bsmL + kp * 1040 + lane * 32) = L0;
        *(uint4*)(bsmL + kp * 1040 + lane * 32 + 16) = L1;
    }
    __syncthreads();

    float d[4][4][4];
#pragma unroll
    for (int mf = 0; mf < 4; mf++)
#pragma unroll
        for (int nf = 0; nf < 4; nf++)
#pragma unroll
            for (int q = 0; q < 4; q++) d[mf][nf][q] = 0.f;

    for (int c = 0; c < 12; c++) {
        float4 p0, p1, p2, p3;
        bool more = (c < 11);
        if (more) {
            const float* r0 = X + (size_t)((c + 1) * 16 + 2 * kp) * HW + px8;
            const float* r1 = r0 + HW;
            p0 = *(const float4*)r0; p1 = *(const float4*)(r0 + 4);
            p2 = *(const float4*)r1; p3 = *(const float4*)(r1 + 4);
        }
        unsigned BH0[4], BH1[4], BL0[4], BL1[4];
#pragma unroll
        for (int nf = 0; nf < 4; nf++) {
            int col = (pxw + nf * 8 + lr) * 4;
            const char* ph = bsmH + lc * 1040 + col;
            const char* pl = bsmL + lc * 1040 + col;
            BH0[nf] = *(const unsigned*)ph;
            BH1[nf] = *(const unsigned*)(ph + 4 * 1040);
            BL0[nf] = *(const unsigned*)pl;
            BL1[nf] = *(const unsigned*)(pl + 4 * 1040);
        }
#pragma unroll
        for (int mf = 0; mf < 4; mf++) {
            const char* ah = wsmH + (mf * 16 + lr) * 400 + c * 32 + lc * 4;
            const char* al = wsmL + (mf * 16 + lr) * 400 + c * 32 + lc * 4;
            unsigned AH0 = *(const unsigned*)ah;
            unsigned AH1 = *(const unsigned*)(ah + 8 * 400);
            unsigned AH2 = *(const unsigned*)(ah + 16);
            unsigned AH3 = *(const unsigned*)(ah + 8 * 400 + 16);
            unsigned AL0 = *(const unsigned*)al;
            unsigned AL1 = *(const unsigned*)(al + 8 * 400);
            unsigned AL2 = *(const unsigned*)(al + 16);
            unsigned AL3 = *(const unsigned*)(al + 8 * 400 + 16);
#pragma unroll
            for (int nf = 0; nf < 4; nf++) {
                mma_bf16(d[mf][nf], AH0, AH1, AH2, AH3, BH0[nf], BH1[nf]);
                mma_bf16(d[mf][nf], AH0, AH1, AH2, AH3, BL0[nf], BL1[nf]);
                mma_bf16(d[mf][nf], AL0, AL1, AL2, AL3, BH0[nf], BH1[nf]);
            }
        }
        __syncthreads();
        if (more) {
            uint4 H0, L0, H1, L1;
            H0.x = packhl(p0.x, p2.x, L0.x); H0.y = packhl(p0.y, p2.y, L0.y);
            H0.z = packhl(p0.z, p2.z, L0.z); H0.w = packhl(p0.w, p2.w, L0.w);
            H1.x = packhl(p1.x, p3.x, L1.x); H1.y = packhl(p1.y, p3.y, L1.y);
            H1.z = packhl(p1.z, p3.z, L1.z); H1.w = packhl(p1.w, p3.w, L1.w);
            *(uint4*)(bsmH + kp * 1040 + lane * 32) = H0;
            *(uint4*)(bsmH + kp * 1040 + lane * 32 + 16) = H1;
            *(uint4*)(bsmL + kp * 1040 + lane * 32) = L0;
            *(uint4*)(bsmL + kp * 1040 + lane * 32 + 16) = L1;
        }
        __syncthreads();
    }

    if (EPI == 1) {
#pragma unroll
        for (int mf = 0; mf < 4; mf++) {
            int oc = mf * 16 + lr;
#pragma unroll
            for (int nf = 0; nf < 4; nf++) {
                int px = px0 + pxw + nf * 8 + 2 * lc;
                *(float2*)&outPlanar[(size_t)(b * 64 + oc) * HW + px] =
                    make_float2(d[mf][nf][0], d[mf][nf][1]);
                *(float2*)&outPlanar[(size_t)(b * 64 + oc + 8) * HW + px] =
                    make_float2(d[mf][nf][2], d[mf][nf][3]);
            }
        }
    } else {
        char* est = sm + warp * 8704;   // [32 px][272 B rows, 16B-aligned]
#pragma unroll
        for (int mf = 0; mf < 4; mf++) {
            int col0 = permCol(mf * 16 + lr);
            int col8 = permCol(mf * 16 + lr + 8);
#pragma unroll
            for (int nf = 0; nf < 4; nf++) {
                int pxl = nf * 8 + 2 * lc;
#pragma unroll
                for (int e = 0; e < 2; e++) {
                    {
                        float v = d[mf][nf][e];
                        __nv_bfloat16 h = __float2bfloat16_rn(v);
                        *(__nv_bfloat16*)(est + (pxl + e) * 272 + col0 * 2) = h;
                        *(__nv_bfloat16*)(est + (pxl + e) * 272 + (64 + col0) * 2) =
                            __float2bfloat16_rn(v - __bfloat162float(h));
                    }
                    {
                        float v = d[mf][nf][2 + e];
                        __nv_bfloat16 h = __float2bfloat16_rn(v);
                        *(__nv_bfloat16*)(est + (pxl + e) * 272 + col8 * 2) = h;
                        *(__nv_bfloat16*)(est + (pxl + e) * 272 + (64 + col8) * 2) =
                            __float2bfloat16_rn(v - __bfloat162float(h));
                    }
                }
            }
        }
        __syncthreads();
#pragma unroll
        for (int r = 0; r < 16; r++) {
            int pxl = r * 2 + (lane >> 4);
            int ch = lane & 15;
            uint4 v = *(const uint4*)(sm + warp * 8704 + pxl * 272 + ch * 16);
            *(uint4*)((char*)outCL + ((size_t)b * HW + px0 + pxw + pxl) * 256 + ch * 16) = v;
        }
    }
}

// ---------------- mid conv: 64->64, KxK, tensor-core bf16 hi/lo ----------------
// Warp tile M=64px x N=64oc (all output channels) -> 83 B of operand traffic
// per HMMA (was 125), lifting the L1-bandwidth-limited tensor ceiling.
// CTA: 256 thr, output tile 32x16 px; barrier-free tap loop.
template<int R>
__global__ void __launch_bounds__(256) k_mconv(
        const __nv_bfloat16* __restrict__ wc,
        float* __restrict__ out, int brBase) {
    constexpr int K = 2 * R + 1, K2 = K * K;
    constexpr int TWX = 32 + 2 * R, TWY = 16 + 2 * R, ROWS = TWX * TWY;
    constexpr int RB = 272;
    extern __shared__ char smem[];
    char* tile = smem;

    int tid = threadIdx.x;
    int b = blockIdx.z;
    int x0 = blockIdx.x * 32, y0 = blockIdx.y * 16;
    int warp = tid >> 5, lane = tid & 31;   // warp = wm (0..7)
    int lr = lane >> 2, lc = lane & 3;

    {
        const __nv_bfloat16* src = g_hc + (size_t)b * HW * 128;
        for (int r0 = 0; r0 < ROWS; r0 += 16) {
            int row = r0 + (tid >> 4);
            if (row < ROWS) {
                int gy = y0 - R + row / TWX;
                int gx = x0 - R + row % TWX;
                uint4 v = make_uint4(0u, 0u, 0u, 0u);
                if (gy >= 0 && gy < 256 && gx >= 0 && gx < 256)
                    v = *(const uint4*)(src + ((size_t)gy * 256 + gx) * 128 + (tid & 15) * 8);
                *(uint4*)(tile + row * RB + (tid & 15) * 16) = v;
            }
        }
    }
    __syncthreads();   // only barrier

    float d[4][8][4];
#pragma unroll
    for (int f = 0; f < 4; f++)
#pragma unroll
        for (int n = 0; n < 8; n++)
#pragma unroll
            for (int q = 0; q < 4; q++) d[f][n][q] = 0.f;

    for (int tap = 0; tap < K2; tap++) {
        int ky = tap / K, kx = tap % K;
        const char* wt = (const char*)(wc + (size_t)tap * 64 * 128) + lr * 256 + lc * 8;
        int abase[4];
#pragma unroll
        for (int f = 0; f < 4; f++)
            abase[f] = (((warp * 2 + (f >> 1) + ky) * TWX) + ((f & 1) * 16) + lr + kx) * RB + lc * 8;

#pragma unroll
        for (int c = 0; c < 4; c++) {
            int co = c * 32;
            // B fragments for ALL 8 n-tiles (gmem, L1/L2-hot)
            uint2 BH[8], BL[8];
#pragma unroll
            for (int n = 0; n < 8; n++) {
                const char* p = wt + n * 8 * 256 + co;
                BH[n] = __ldg((const uint2*)p);
                BL[n] = __ldg((const uint2*)(p + 128));
            }
#pragma unroll
            for (int f = 0; f < 4; f++) {
                const char* p = tile + abase[f] + co;
                uint2 AH0 = *(const uint2*)p;
                uint2 AH1 = *(const uint2*)(p + 8 * RB);
                uint2 AL0 = *(const uint2*)(p + 128);
                uint2 AL1 = *(const uint2*)(p + 128 + 8 * RB);
#pragma unroll
                for (int n = 0; n < 8; n++) {
                    mma_bf16(d[f][n], AH0.x, AH1.x, AH0.y, AH1.y, BH[n].x, BH[n].y);
                    mma_bf16(d[f][n], AH0.x, AH1.x, AH0.y, AH1.y, BL[n].x, BL[n].y);
                    mma_bf16(d[f][n], AL0.x, AL1.x, AL0.y, AL1.y, BH[n].x, BH[n].y);
                }
            }
        }
    }

#pragma unroll
    for (int f = 0; f < 4; f++) {
        int y = y0 + warp * 2 + (f >> 1);
        int x = x0 + (f & 1) * 16 + lr;
#pragma unroll
        for (int n = 0; n < 8; n++) {
            int oc = n * 8 + lc * 2;
            float* o0 = out + ((size_t)(b * 192 + brBase + oc) * HW + y * 256 + x);
            o0[0]       = fmaxf(d[f][n][0], 0.f);
            o0[8]       = fmaxf(d[f][n][2], 0.f);
            o0[HW]      = fmaxf(d[f][n][1], 0.f);
            o0[HW + 8]  = fmaxf(d[f][n][3], 0.f);
        }
    }
}

// ---------------- BN stats ----------------
__global__ void k_bnsum() {
    int c = blockIdx.x >> 2, seg = blockIdx.x & 3, tid = threadIdx.x;
    int base = seg * 32768;
    double s[4] = {0, 0, 0, 0}, s2[4] = {0, 0, 0, 0};
    for (int u = 0; u < 32; u++) {
        int t = base + u * 1024 + tid * 4;
#pragma unroll
        for (int q = 0; q < 4; q++) {
            int tt = t + q;
            int bb = tt >> 16, p = tt & (HW - 1);
            float v = g_m64[(size_t)(bb * 64 + c) * HW + p];
            s[q] += v; s2[q] += (double)v * v;
        }
    }
    double ss = (s[0] + s[1]) + (s[2] + s[3]);
    double ss2 = (s2[0] + s2[1]) + (s2[2] + s2[3]);
    __shared__ double sh1[256], sh2[256];
    sh1[tid] = ss; sh2[tid] = ss2; __syncthreads();
    for (int st = 128; st > 0; st >>= 1) {
        if (tid < st) { sh1[tid] += sh1[tid + st]; sh2[tid] += sh2[tid + st]; }
        __syncthreads();
    }
    if (tid == 0) { g_ps1[c][seg] = sh1[0]; g_ps2[c][seg] = sh2[0]; }
}

__global__ void k_bncoef(const float* __restrict__ bn_g, const float* __restrict__ bn_b) {
    int c = threadIdx.x;
    double N = (double)(Bn * HW);
    double s1 = (g_ps1[c][0] + g_ps1[c][1]) + (g_ps1[c][2] + g_ps1[c][3]);
    double s2 = (g_ps2[c][0] + g_ps2[c][1]) + (g_ps2[c][2] + g_ps2[c][3]);
    double mean = s1 / N;
    double var = s2 / N - mean * mean;
    float a = (float)((double)bn_g[c] / sqrt(var + 1e-5));
    g_a[c] = a;
    g_bc[c] = bn_b[c] - (float)mean * a;
}

__global__ void k_ymean() {
    int c = blockIdx.x, b = blockIdx.y, tid = threadIdx.x;
    float a = g_a[c], bc = g_bc[c];
    const float* mp = g_m64 + (size_t)(b * 64 + c) * HW;
    double s[4] = {0, 0, 0, 0};
    for (int p = tid * 4; p < HW; p += 1024) {
#pragma unroll
        for (int q = 0; q < 4; q++)
            s[q] += (double)fmaxf(fmaf(a, mp[p + q], bc), 0.f);
    }
    __shared__ double sh[256];
    sh[tid] = (s[0] + s[1]) + (s[2] + s[3]); __syncthreads();
    for (int st = 128; st > 0; st >>= 1) {
        if (tid < st) sh[tid] += sh[tid + st];
        __syncthreads();
    }
    if (tid == 0) g_ym[b * 64 + c] = sh[0] / (double)HW;
}

__global__ void k_se(const float* __restrict__ se1, const float* __restrict__ se2) {
    __shared__ float t1[2][4];
    int tid = threadIdx.x;
    for (int b = 0; b < 2; b++) {
        if (tid < 4) {
            float s = 0.f;
            for (int c = 0; c < 64; c++) s += se1[tid * 64 + c] * (float)g_ym[b * 64 + c];
            t1[b][tid] = fmaxf(s, 0.f);
        }
    }
    __syncthreads();
    for (int b = 0; b < 2; b++) {
        float z = 0.f;
        for (int j = 0; j < 4; j++) z += se2[tid * 4 + j] * t1[b][j];
        g_y[b * 64 + tid] = 1.f / (1.f + expf(-z));
    }
}

// ---------------- final: interior fast path + 3 accumulators ----------------
__global__ void k_final(const float* __restrict__ wf, float* __restrict__ out) {
    __shared__ float wy[576], sa[64], sb[64];
    int b = blockIdx.y;
    int tid = threadIdx.x;
    for (int t = tid; t < 576; t += 256) {
        int c = t / 9;
        wy[t] = __ldg(&wf[t]) * g_y[b * 64 + c];
    }
    if (tid < 64) { sa[tid] = g_a[tid]; sb[tid] = g_bc[tid]; }
    __syncthreads();
    int bx = blockIdx.x;
    int tx0 = (bx & 15) * 16, ty0 = (bx >> 4) * 16;
    int i = ty0 + (tid >> 4), j = tx0 + (tid & 15);
    const float* mb = g_m64 + (size_t)b * 64 * HW;
    float a0 = 0.f, a1 = 0.f, a2 = 0.f;
    bool interior = (tx0 > 0) && (tx0 < 240) && (ty0 > 0) && (ty0 < 240);
    if (interior) {
        const float* p0 = mb + (i - 1) * 256 + (j - 1);
        for (int c = 0; c < 64; c++) {
            float a = sa[c], bc = sb[c];
            const float* pc = p0 + (size_t)c * HW;
            const float* wt = wy + c * 9;
            float r;
            r = fmaxf(fmaf(a, __ldg(&pc[0]),   bc), 0.f); a0 = fmaf(wt[0], r, a0);
            r = fmaxf(fmaf(a, __ldg(&pc[1]),   bc), 0.f); a1 = fmaf(wt[1], r, a1);
            r = fmaxf(fmaf(a, __ldg(&pc[2]),   bc), 0.f); a2 = fmaf(wt[2], r, a2);
            r = fmaxf(fmaf(a, __ldg(&pc[256]), bc), 0.f); a0 = fmaf(wt[3], r, a0);
            r = fmaxf(fmaf(a, __ldg(&pc[257]), bc), 0.f); a1 = fmaf(wt[4], r, a1);
            r = fmaxf(fmaf(a, __ldg(&pc[258]), bc), 0.f); a2 = fmaf(wt[5], r, a2);
            r = fmaxf(fmaf(a, __ldg(&pc[512]), bc), 0.f); a0 = fmaf(wt[6], r, a0);
            r = fmaxf(fmaf(a, __ldg(&pc[513]), bc), 0.f); a1 = fmaf(wt[7], r, a1);
            r = fmaxf(fmaf(a, __ldg(&pc[514]), bc), 0.f); a2 = fmaf(wt[8], r, a2);
        }
    } else {
        for (int c = 0; c < 64; c++) {
            float a = sa[c], bc = sb[c];
            const float* mc = mb + (size_t)c * HW;
#pragma unroll
            for (int ky = 0; ky < 3; ky++) {
                int yy = i + ky - 1; if (yy < 0 || yy > 255) continue;
#pragma unroll
                for (int kx = 0; kx < 3; kx++) {
                    int xx = j + kx - 1; if (xx < 0 || xx > 255) continue;
                    float v = __ldg(&mc[yy * 256 + xx]);
                    float r = fmaxf(fmaf(a, v, bc), 0.f);
                    a0 = fmaf(wy[c * 9 + ky * 3 + kx], r, a0);
                }
            }
        }
    }
    int p = i * 256 + j;
    out[b * HW + p] = g_xp[b * HW + p] - ((a0 + a1) + a2);
}

// ---------------- launch ----------------
extern "C" void kernel_launch(void* const* d_in, const int* in_sizes, int n_in,
                              void* d_out, int out_size) {
    const float* x    = (const float*)d_in[0];
    const float* w_i3 = (const float*)d_in[1];
    const float* w_i5 = (const float*)d_in[2];
    const float* w_i7 = (const float*)d_in[3];
    const float* w_p1 = (const float*)d_in[4];
    const float* wb3  = (const float*)d_in[5];
    const float* wb5  = (const float*)d_in[6];
    const float* wb7  = (const float*)d_in[7];
    const float* wbp  = (const float*)d_in[8];
    const float* bn_g = (const float*)d_in[9];
    const float* bn_b = (const float*)d_in[10];
    const float* se1  = (const float*)d_in[11];
    const float* se2  = (const float*)d_in[12];
    const float* wf   = (const float*)d_in[13];
    float* out = (float*)d_out;

    float *xp, *h192, *m192, *m64;
    cudaGetSymbolAddress((void**)&xp,   g_xp);
    cudaGetSymbolAddress((void**)&h192, g_h192);
    cudaGetSymbolAddress((void**)&m192, g_m192);
    cudaGetSymbolAddress((void**)&m64,  g_m64);
    __nv_bfloat16 *hc, *wc3, *wc5, *wc7;
    cudaGetSymbolAddress((void**)&hc,  g_hc);
    cudaGetSymbolAddress((void**)&wc3, g_wc3);
    cudaGetSymbolAddress((void**)&wc5, g_wc5);
    cudaGetSymbolAddress((void**)&wc7, g_wc7);

    const int smem1 = (34 * 18) * 272;   // 166464
    const int smem2 = (36 * 20) * 272;   // 195840
    const int smem3 = (38 * 22) * 272;   // 227392
    const int smemP = 8 * 8704;
    cudaFuncSetAttribute(k_mconv<1>, cudaFuncAttributeMaxDynamicSharedMemorySize, smem1);
    cudaFuncSetAttribute(k_mconv<2>, cudaFuncAttributeMaxDynamicSharedMemorySize, smem2);
    cudaFuncSetAttribute(k_mconv<3>, cudaFuncAttributeMaxDynamicSharedMemorySize, smem3);
    cudaFuncSetAttribute(k_p1x1<0>, cudaFuncAttributeMaxDynamicSharedMemorySize, smemP);
    cudaFuncSetAttribute(k_p1x1<1>, cudaFuncAttributeMaxDynamicSharedMemorySize, smemP);

    // Launch order keeps k_mconv<3> at my-index 3 (ncu captures it).
    k_pre<<<512, 256>>>(x);                                                 // 0
    k_conv1f<<<dim3(64, 48), 256>>>(xp, w_i3, w_i5, w_i7, h192);            // 1
    k_p1x1<0><<<dim3(256, Bn + 1), 256, smemP>>>(h192, w_p1, nullptr, hc,
                                                 wb3, wb5, wb7,
                                                 wc3, wc5, wc7);            // 2
    dim3 gm(8, 16, Bn);
    k_mconv<3><<<gm, 256, smem3>>>(wc7, m192, 128);                         // 3 (profiled)
    k_mconv<1><<<gm, 256, smem1>>>(wc3, m192, 0);                           // 4
    k_mconv<2><<<gm, 256, smem2>>>(wc5, m192, 64);                          // 5
    k_p1x1<1><<<dim3(256, Bn), 256, smemP>>>(m192, wbp, m64, nullptr,
                                             nullptr, nullptr, nullptr,
                                             nullptr, nullptr, nullptr);    // 6
    k_bnsum<<<256, 256>>>();                                                // 7
    k_bncoef<<<1, 64>>>(bn_g, bn_b);                                        // 8
    k_ymean<<<dim3(64, 2), 256>>>();                                        // 9
    k_se<<<1, 64>>>(se1, se2);                                              // 10
    k_final<<<dim3(256, 2), 256>>>(wf, out);                                // 11
}

// round 14
// speedup vs baseline: 1.4000x; 1.2384x over previous
#include <cuda_runtime.h>
#include <cuda_bf16.h>
#include <cuda_fp16.h>
#include <math.h>

#define HW 65536
#define Bn 2

// ---------------- scratch ----------------
__device__ float g_xp[Bn * HW];
__device__ float g_h192[Bn * 192 * HW];
__device__ float g_m192[Bn * 192 * HW];
__device__ float g_m64[Bn * 64 * HW];
__device__ double g_ps1[64][4], g_ps2[64][4];
__device__ float g_a[64], g_bc[64];
__device__ double g_ym[Bn * 64];
__device__ float g_y[Bn * 64];
// channel-last fp16 input for mid convs: [b][px][64]
__device__ __half g_hc[(size_t)Bn * HW * 64];
// per-tap weights, rows [oc][hi 64 | lo 64] fp16 (permuted ic order)
__device__ __half g_wc3[9 * 64 * 128];
__device__ __half g_wc5[25 * 64 * 128];
__device__ __half g_wc7[49 * 64 * 128];

// permuted within-16 element index (k-pair interleave so LDS.64 = (k01,k89) frag regs)
__device__ __host__ __forceinline__ int permCol(int ic) {
    int jj = ic & 15, q = jj >> 1, e = jj & 1;
    int sp = (q < 4) ? 2 * q : 2 * (q - 4) + 1;
    return (ic & ~15) + 2 * sp + e;
}

// ---------------- preprocess ----------------
__device__ __forceinline__ float blendf(float v) {
    float g = fminf(fmaxf((v + 1.0f) * 0.5f, 1e-6f), 1.0f);
    return 0.6f * g + 0.4f * g * sqrtf(g);
}

__global__ void k_pre(const float* __restrict__ x) {
    int idx = blockIdx.x * blockDim.x + threadIdx.x;
    if (idx >= Bn * HW) return;
    int b = idx >> 16, p = idx & (HW - 1);
    int i = p >> 8, j = p & 255;
    const float* xb = x + b * HW;
    float c = blendf(xb[p]);
    const int   di[13] = {-2,-1,-1,-1, 0, 0, 0, 0, 0, 1, 1, 1, 2};
    const int   dj[13] = { 0,-1, 0, 1,-2,-1, 0, 1, 2,-1, 0, 1, 0};
    const float sw[13] = {0.99920032f,0.99960008f,0.99980002f,0.99960008f,
                          0.99920032f,0.99980002f,1.0f,0.99980002f,0.99920032f,
                          0.99960008f,0.99980002f,0.99960008f,0.99920032f};
    float num = 0.f, den = 0.f;
#pragma unroll
    for (int t = 0; t < 13; t++) {
        int ri = i + di[t]; ri = ri < 0 ? -ri : (ri > 255 ? 510 - ri : ri);
        int rj = j + dj[t]; rj = rj < 0 ? -rj : (rj > 255 ? 510 - rj : rj);
        float sh = blendf(xb[ri * 256 + rj]);
        float d = sh - c;
        float w = sw[t] * expf(-200.0f * d * d);
        num = fmaf(w, sh, num);
        den += w;
    }
    g_xp[idx] = num / den;
}

// ---------------- fused input convs: 1 -> 64 x three kernel sizes ----------------
template<int R>
__device__ __forceinline__ void conv1_body(
        float* tile, float* ws,
        const float* __restrict__ in, const float* __restrict__ w,
        float* __restrict__ out, int brBase, int ysub) {
    constexpr int K = 2 * R + 1, K2 = K * K;
    constexpr int TW = 32 + 2 * R;
    int bx = blockIdx.x;
    int tx0 = (bx & 7) * 32, ty0 = (bx >> 3) * 32;
    int b = ysub >> 3, ocg = ysub & 7;
    int oc0 = ocg * 8;
    int tid = threadIdx.x;            // 256
    const float* icp = in + (size_t)b * HW;
    for (int t = tid; t < TW * TW; t += 256) {
        int yy = ty0 - R + t / TW, xx = tx0 - R + t % TW;
        tile[t] = (yy >= 0 && yy < 256 && xx >= 0 && xx < 256)
                ? __ldg(&icp[yy * 256 + xx]) : 0.f;
    }
    for (int t = tid; t < 8 * K2; t += 256) {
        int o = t / K2;
        ws[t] = w[(size_t)(oc0 + o) * K2 + (t - o * K2)];
    }
    __syncthreads();
    int row = tid >> 3, xq = (tid & 7) * 4;
    float acc[8][4];
#pragma unroll
    for (int o = 0; o < 8; o++)
#pragma unroll
        for (int q = 0; q < 4; q++) acc[o][q] = 0.f;
#pragma unroll
    for (int ky = 0; ky < K; ky++) {
#pragma unroll
        for (int kx = 0; kx < K; kx++) {
            int base = (row + ky) * TW + xq + kx;
            float t0 = tile[base], t1 = tile[base + 1];
            float t2 = tile[base + 2], t3 = tile[base + 3];
#pragma unroll
            for (int o = 0; o < 8; o++) {
                float wv = ws[o * K2 + ky * K + kx];
                acc[o][0] = fmaf(t0, wv, acc[o][0]);
                acc[o][1] = fmaf(t1, wv, acc[o][1]);
                acc[o][2] = fmaf(t2, wv, acc[o][2]);
                acc[o][3] = fmaf(t3, wv, acc[o][3]);
            }
        }
    }
    size_t ob = (size_t)(b * 192 + brBase + oc0) * HW + (ty0 + row) * 256 + tx0 + xq;
#pragma unroll
    for (int o = 0; o < 8; o++)
#pragma unroll
        for (int q = 0; q < 4; q++)
            out[ob + (size_t)o * HW + q] = fmaxf(acc[o][q], 0.f);
}

// grid (64, 48): y>>4 selects branch (R=1/2/3), y&15 = b*8 + ocg.
__global__ void __launch_bounds__(256) k_conv1f(
        const float* __restrict__ xp,
        const float* __restrict__ w3, const float* __restrict__ w5,
        const float* __restrict__ w7, float* __restrict__ out) {
    __shared__ float tile[38 * 38];
    __shared__ float ws[8 * 49];
    int br = blockIdx.y >> 4;
    int ysub = blockIdx.y & 15;
    if (br == 0)      conv1_body<1>(tile, ws, xp, w3, out, 0,   ysub);
    else if (br == 1) conv1_body<2>(tile, ws, xp, w5, out, 64,  ysub);
    else              conv1_body<3>(tile, ws, xp, w7, out, 128, ysub);
}

// ---------------- mma helpers ----------------
__device__ __forceinline__ void mma_bf16(float* d, unsigned a0, unsigned a1,
                                         unsigned a2, unsigned a3,
                                         unsigned b0, unsigned b1) {
    asm("mma.sync.aligned.m16n8k16.row.col.f32.bf16.bf16.f32 "
        "{%0,%1,%2,%3},{%4,%5,%6,%7},{%8,%9},{%0,%1,%2,%3};"
        : "+f"(d[0]), "+f"(d[1]), "+f"(d[2]), "+f"(d[3])
        : "r"(a0), "r"(a1), "r"(a2), "r"(a3), "r"(b0), "r"(b1));
}
__device__ __forceinline__ void mma_f16(float* d, unsigned a0, unsigned a1,
                                        unsigned a2, unsigned a3,
                                        unsigned b0, unsigned b1) {
    asm("mma.sync.aligned.m16n8k16.row.col.f32.f16.f16.f32 "
        "{%0,%1,%2,%3},{%4,%5,%6,%7},{%8,%9},{%0,%1,%2,%3};"
        : "+f"(d[0]), "+f"(d[1]), "+f"(d[2]), "+f"(d[3])
        : "r"(a0), "r"(a1), "r"(a2), "r"(a3), "r"(b0), "r"(b1));
}

// hi/lo split + pack two values into bf16x2 words (1x1 conv staging)
__device__ __forceinline__ unsigned packhl(float a, float b, unsigned& lo) {
    __nv_bfloat16 ha = __float2bfloat16_rn(a);
    __nv_bfloat16 hb = __float2bfloat16_rn(b);
    float la = a - __bfloat162float(ha);
    float lb = b - __bfloat162float(hb);
    __nv_bfloat162 l2 = __float22bfloat162_rn(make_float2(la, lb));
    lo = *reinterpret_cast<unsigned*>(&l2);
    __nv_bfloat162 h2; h2.x = ha; h2.y = hb;
    return *reinterpret_cast<unsigned*>(&h2);
}

// ---------------- planar 1x1 conv via tensor cores: 192 -> 64 ----------------
// GEMM internals bf16 hi/lo 3-pass (unchanged, rel_err ~1e-6).
// EPI 0: write channel-last fp16 SINGLE (g_hc format, 128 B/px); extra grid
//        slice (blockIdx.y == Bn) performs ALL mid-conv weight conversion (fp16 hi/lo).
// EPI 1: planar fp32 store.
template<int EPI>
__global__ void __launch_bounds__(256) k_p1x1(
        const float* __restrict__ in, const float* __restrict__ w,
        float* __restrict__ outPlanar, __half* __restrict__ outCL,
        const float* __restrict__ wb3, const float* __restrict__ wb5,
        const float* __restrict__ wb7,
        __half* __restrict__ wc3, __half* __restrict__ wc5,
        __half* __restrict__ wc7) {
    extern __shared__ char sm[];

    // ---- weight-conversion side slice (EPI 0 only) ----
    if (EPI == 0 && blockIdx.y == Bn) {
        int gid = blockIdx.x * 256 + threadIdx.x;   // 0..65535
        for (int idx = gid; idx < 83 * 4096; idx += 65536) {
            int u = idx >> 12, r = idx & 4095;
            int oc = r >> 6, ic = r & 63;
            const float* wsrc; __half* wdst; int K2, tap;
            if (u < 9)       { wsrc = wb3; wdst = wc3; K2 = 9;  tap = u; }
            else if (u < 34) { wsrc = wb5; wdst = wc5; K2 = 25; tap = u - 9; }
            else             { wsrc = wb7; wdst = wc7; K2 = 49; tap = u - 34; }
            float v = wsrc[((size_t)oc * 64 + ic) * K2 + tap];
            __half hi = __float2half_rn(v);
            __half lo = __float2half_rn(v - __half2float(hi));
            __half* row = wdst + ((size_t)tap * 64 + oc) * 128;
            int col = permCol(ic);
            row[col] = hi;
            row[64 + col] = lo;
        }
        return;
    }

    char* wsmH = sm;
    char* wsmL = sm + 25600;
    char* bsmH = sm + 51200;
    char* bsmL = sm + 59520;

    int tid = threadIdx.x;
    int b = blockIdx.y;
    int px0 = blockIdx.x * 256;
    int warp = tid >> 5, lane = tid & 31;
    int lr = lane >> 2, lc = lane & 3;
    int kp = warp;
    int px8 = lane * 8;
    int pxw = warp * 32;

    const float* X = in + (size_t)b * 192 * HW + px0;

    // ---- load weights, split hi/lo (bf16) ----
    {
        int oc = tid >> 2, seg = tid & 3;
        const float* wr = w + oc * 192 + seg * 48;
        __nv_bfloat16* dh = (__nv_bfloat16*)(wsmH + oc * 400) + seg * 48;
        __nv_bfloat16* dl = (__nv_bfloat16*)(wsmL + oc * 400) + seg * 48;
        for (int i = 0; i < 48; i++) {
            float v = __ldg(&wr[i]);
            __nv_bfloat16 h = __float2bfloat16_rn(v);
            dh[i] = h;
            dl[i] = __float2bfloat16_rn(v - __bfloat162float(h));
        }
    }
    // ---- stage chunk 0 ----
    {
        const float* r0 = X + (size_t)(2 * kp) * HW + px8;
        const float* r1 = r0 + HW;
        float4 p0 = *(const float4*)r0, p1 = *(const float4*)(r0 + 4);
        float4 p2 = *(const float4*)r1, p3 = *(const float4*)(r1 + 4);
        uint4 H0, L0, H1, L1;
        H0.x = packhl(p0.x, p2.x, L0.x); H0.y = packhl(p0.y, p2.y, L0.y);
        H0.z = packhl(p0.z, p2.z, L0.z); H0.w = packhl(p0.w, p2.w, L0.w);
        H1.x = packhl(p1.x, p3.x, L1.x); H1.y = packhl(p1.y, p3.y, L1.y);
        H1.z = packhl(p1.z, p3.z, L1.z); H1.w = packhl(p1.w, p3.w, L1.w);
        *(uint4*)(bsmH + kp * 1040 + lane * 32) = H0;
        *(uint4*)(bsmH + kp * 1040 + lane * 32 + 16) = H1;
        *(uint4*)(bsmL + kp * 1040 + lane * 32) = L0;
        *(uint4*)(bsmL + kp * 1040 + lane * 32 + 16) = L1;
    }
    __syncthreads();

    float d[4][4][4];
#pragma unroll
    for (int mf = 0; mf < 4; mf++)
#pragma unroll
        for (int nf = 0; nf < 4; nf++)
#pragma unroll
            for (int q = 0; q < 4; q++) d[mf][nf][q] = 0.f;

    for (int c = 0; c < 12; c++) {
        float4 p0, p1, p2, p3;
        bool more = (c < 11);
        if (more) {
            const float* r0 = X + (size_t)((c + 1) * 16 + 2 * kp) * HW + px8;
            const float* r1 = r0 + HW;
            p0 = *(const float4*)r0; p1 = *(const float4*)(r0 + 4);
            p2 = *(const float4*)r1; p3 = *(const float4*)(r1 + 4);
        }
        unsigned BH0[4], BH1[4], BL0[4], BL1[4];
#pragma unroll
        for (int nf = 0; nf < 4; nf++) {
            int col = (pxw + nf * 8 + lr) * 4;
            const char* ph = bsmH + lc * 1040 + col;
            const char* pl = bsmL + lc * 1040 + col;
            BH0[nf] = *(const unsigned*)ph;
            BH1[nf] = *(const unsigned*)(ph + 4 * 1040);
            BL0[nf] = *(const unsigned*)pl;
            BL1[nf] = *(const unsigned*)(pl + 4 * 1040);
        }
#pragma unroll
        for (int mf = 0; mf < 4; mf++) {
            const char* ah = wsmH + (mf * 16 + lr) * 400 + c * 32 + lc * 4;
            const char* al = wsmL + (mf * 16 + lr) * 400 + c * 32 + lc * 4;
            unsigned AH0 = *(const unsigned*)ah;
            unsigned AH1 = *(const unsigned*)(ah + 8 * 400);
            unsigned AH2 = *(const unsigned*)(ah + 16);
            unsigned AH3 = *(const unsigned*)(ah + 8 * 400 + 16);
            unsigned AL0 = *(const unsigned*)al;
            unsigned AL1 = *(const unsigned*)(al + 8 * 400);
            unsigned AL2 = *(const unsigned*)(al + 16);
            unsigned AL3 = *(const unsigned*)(al + 8 * 400 + 16);
#pragma unroll
            for (int nf = 0; nf < 4; nf++) {
                mma_bf16(d[mf][nf], AH0, AH1, AH2, AH3, BH0[nf], BH1[nf]);
                mma_bf16(d[mf][nf], AH0, AH1, AH2, AH3, BL0[nf], BL1[nf]);
                mma_bf16(d[mf][nf], AL0, AL1, AL2, AL3, BH0[nf], BH1[nf]);
            }
        }
        __syncthreads();
        if (more) {
            uint4 H0, L0, H1, L1;
            H0.x = packhl(p0.x, p2.x, L0.x); H0.y = packhl(p0.y, p2.y, L0.y);
            H0.z = packhl(p0.z, p2.z, L0.z); H0.w = packhl(p0.w, p2.w, L0.w);
            H1.x = packhl(p1.x, p3.x, L1.x); H1.y = packhl(p1.y, p3.y, L1.y);
            H1.z = packhl(p1.z, p3.z, L1.z); H1.w = packhl(p1.w, p3.w, L1.w);
            *(uint4*)(bsmH + kp * 1040 + lane * 32) = H0;
            *(uint4*)(bsmH + kp * 1040 + lane * 32 + 16) = H1;
            *(uint4*)(bsmL + kp * 1040 + lane * 32) = L0;
            *(uint4*)(bsmL + kp * 1040 + lane * 32 + 16) = L1;
        }
        __syncthreads();
    }

    if (EPI == 1) {
#pragma unroll
        for (int mf = 0; mf < 4; mf++) {
            int oc = mf * 16 + lr;
#pragma unroll
            for (int nf = 0; nf < 4; nf++) {
                int px = px0 + pxw + nf * 8 + 2 * lc;
                *(float2*)&outPlanar[(size_t)(b * 64 + oc) * HW + px] =
                    make_float2(d[mf][nf][0], d[mf][nf][1]);
                *(float2*)&outPlanar[(size_t)(b * 64 + oc + 8) * HW + px] =
                    make_float2(d[mf][nf][2], d[mf][nf][3]);
            }
        }
    } else {
        // channel-last fp16 single via smem staging (g_hc format, permCol)
        char* est = sm + warp * 4608;   // [32 px][144 B rows, 16B-aligned]
#pragma unroll
        for (int mf = 0; mf < 4; mf++) {
            int col0 = permCol(mf * 16 + lr);
            int col8 = permCol(mf * 16 + lr + 8);
#pragma unroll
            for (int nf = 0; nf < 4; nf++) {
                int pxl = nf * 8 + 2 * lc;
#pragma unroll
                for (int e = 0; e < 2; e++) {
                    *(__half*)(est + (pxl + e) * 144 + col0 * 2) =
                        __float2half_rn(d[mf][nf][e]);
                    *(__half*)(est + (pxl + e) * 144 + col8 * 2) =
                        __float2half_rn(d[mf][nf][2 + e]);
                }
            }
        }
        __syncthreads();
#pragma unroll
        for (int r = 0; r < 8; r++) {
            int pxl = r * 4 + (lane >> 3);
            int ch = (lane & 7) * 16;
            uint4 v = *(const uint4*)(sm + warp * 4608 + pxl * 144 + ch);
            *(uint4*)((char*)outCL + ((size_t)b * HW + px0 + pxw + pxl) * 128 + ch) = v;
        }
    }
}

// ---------------- mid conv: 64->64, KxK, fp16 2-pass (A single, B hi/lo) ------
// Warp tile M=64px x N=64oc; CTA 256 thr, output tile 32x16; barrier-free taps.
template<int R>
__global__ void __launch_bounds__(256) k_mconv(
        const __half* __restrict__ wc,
        float* __restrict__ out, int brBase) {
    constexpr int K = 2 * R + 1, K2 = K * K;
    constexpr int TWX = 32 + 2 * R, TWY = 16 + 2 * R, ROWS = TWX * TWY;
    constexpr int RB = 144;             // 64 fp16 = 128 B data + 16 B pad
    extern __shared__ char smem[];
    char* tile = smem;

    int tid = threadIdx.x;
    int b = blockIdx.z;
    int x0 = blockIdx.x * 32, y0 = blockIdx.y * 16;
    int warp = tid >> 5, lane = tid & 31;
    int lr = lane >> 2, lc = lane & 3;

    {
        const __half* src = g_hc + (size_t)b * HW * 64;
        for (int t = tid; t < ROWS * 8; t += 256) {
            int row = t >> 3, chunk = t & 7;
            int gy = y0 - R + row / TWX;
            int gx = x0 - R + row % TWX;
            uint4 v = make_uint4(0u, 0u, 0u, 0u);
            if (gy >= 0 && gy < 256 && gx >= 0 && gx < 256)
                v = *(const uint4*)(src + ((size_t)gy * 256 + gx) * 64 + chunk * 8);
            *(uint4*)(tile + row * RB + chunk * 16) = v;
        }
    }
    __syncthreads();   // only barrier

    float d[4][8][4];
#pragma unroll
    for (int f = 0; f < 4; f++)
#pragma unroll
        for (int n = 0; n < 8; n++)
#pragma unroll
            for (int q = 0; q < 4; q++) d[f][n][q] = 0.f;

    for (int tap = 0; tap < K2; tap++) {
        int ky = tap / K, kx = tap % K;
        const char* wt = (const char*)(wc + (size_t)tap * 64 * 128) + lr * 256 + lc * 8;
        int abase[4];
#pragma unroll
        for (int f = 0; f < 4; f++)
            abase[f] = (((warp * 2 + (f >> 1) + ky) * TWX) + ((f & 1) * 16) + lr + kx) * RB + lc * 8;

#pragma unroll
        for (int c = 0; c < 4; c++) {
            int co = c * 32;
            uint2 BH[8], BL[8];
#pragma unroll
            for (int n = 0; n < 8; n++) {
                const char* p = wt + n * 8 * 256 + co;
                BH[n] = __ldg((const uint2*)p);
                BL[n] = __ldg((const uint2*)(p + 128));
            }
#pragma unroll
            for (int f = 0; f < 4; f++) {
                const char* p = tile + abase[f] + co;
                uint2 A0 = *(const uint2*)p;
                uint2 A1 = *(const uint2*)(p + 8 * RB);
#pragma unroll
                for (int n = 0; n < 8; n++) {
                    mma_f16(d[f][n], A0.x, A1.x, A0.y, A1.y, BH[n].x, BH[n].y);
                    mma_f16(d[f][n], A0.x, A1.x, A0.y, A1.y, BL[n].x, BL[n].y);
                }
            }
        }
    }

#pragma unroll
    for (int f = 0; f < 4; f++) {
        int y = y0 + warp * 2 + (f >> 1);
        int x = x0 + (f & 1) * 16 + lr;
#pragma unroll
        for (int n = 0; n < 8; n++) {
            int oc = n * 8 + lc * 2;
            float* o0 = out + ((size_t)(b * 192 + brBase + oc) * HW + y * 256 + x);
            o0[0]       = fmaxf(d[f][n][0], 0.f);
            o0[8]       = fmaxf(d[f][n][2], 0.f);
            o0[HW]      = fmaxf(d[f][n][1], 0.f);
            o0[HW + 8]  = fmaxf(d[f][n][3], 0.f);
        }
    }
}

// ---------------- BN stats ----------------
__global__ void k_bnsum() {
    int c = blockIdx.x >> 2, seg = blockIdx.x & 3, tid = threadIdx.x;
    int base = seg * 32768;
    double s[4] = {0, 0, 0, 0}, s2[4] = {0, 0, 0, 0};
    for (int u = 0; u < 32; u++) {
        int t = base + u * 1024 + tid * 4;
#pragma unroll
        for (int q = 0; q < 4; q++) {
            int tt = t + q;
            int bb = tt >> 16, p = tt & (HW - 1);
            float v = g_m64[(size_t)(bb * 64 + c) * HW + p];
            s[q] += v; s2[q] += (double)v * v;
        }
    }
    double ss = (s[0] + s[1]) + (s[2] + s[3]);
    double ss2 = (s2[0] + s2[1]) + (s2[2] + s2[3]);
    __shared__ double sh1[256], sh2[256];
    sh1[tid] = ss; sh2[tid] = ss2; __syncthreads();
    for (int st = 128; st > 0; st >>= 1) {
        if (tid < st) { sh1[tid] += sh1[tid + st]; sh2[tid] += sh2[tid + st]; }
        __syncthreads();
    }
    if (tid == 0) { g_ps1[c][seg] = sh1[0]; g_ps2[c][seg] = sh2[0]; }
}

__global__ void k_bncoef(const float* __restrict__ bn_g, const float* __restrict__ bn_b) {
    int c = threadIdx.x;
    double N = (double)(Bn * HW);
    double s1 = (g_ps1[c][0] + g_ps1[c][1]) + (g_ps1[c][2] + g_ps1[c][3]);
    double s2 = (g_ps2[c][0] + g_ps2[c][1]) + (g_ps2[c][2] + g_ps2[c][3]);
    double mean = s1 / N;
    double var = s2 / N - mean * mean;
    float a = (float)((double)bn_g[c] / sqrt(var + 1e-5));
    g_a[c] = a;
    g_bc[c] = bn_b[c] - (float)mean * a;
}

__global__ void k_ymean() {
    int c = blockIdx.x, b = blockIdx.y, tid = threadIdx.x;
    float a = g_a[c], bc = g_bc[c];
    const float* mp = g_m64 + (size_t)(b * 64 + c) * HW;
    double s[4] = {0, 0, 0, 0};
    for (int p = tid * 4; p < HW; p += 1024) {
#pragma unroll
        for (int q = 0; q < 4; q++)
            s[q] += (double)fmaxf(fmaf(a, mp[p + q], bc), 0.f);
    }
    __shared__ double sh[256];
    sh[tid] = (s[0] + s[1]) + (s[2] + s[3]); __syncthreads();
    for (int st = 128; st > 0; st >>= 1) {
        if (tid < st) sh[tid] += sh[tid + st];
        __syncthreads();
    }
    if (tid == 0) g_ym[b * 64 + c] = sh[0] / (double)HW;
}

__global__ void k_se(const float* __restrict__ se1, const float* __restrict__ se2) {
    __shared__ float t1[2][4];
    int tid = threadIdx.x;
    for (int b = 0; b < 2; b++) {
        if (tid < 4) {
            float s = 0.f;
            for (int c = 0; c < 64; c++) s += se1[tid * 64 + c] * (float)g_ym[b * 64 + c];
            t1[b][tid] = fmaxf(s, 0.f);
        }
    }
    __syncthreads();
    for (int b = 0; b < 2; b++) {
        float z = 0.f;
        for (int j = 0; j < 4; j++) z += se2[tid * 4 + j] * t1[b][j];
        g_y[b * 64 + tid] = 1.f / (1.f + expf(-z));
    }
}

// ---------------- final: interior fast path + 3 accumulators ----------------
__global__ void k_final(const float* __restrict__ wf, float* __restrict__ out) {
    __shared__ float wy[576], sa[64], sb[64];
    int b = blockIdx.y;
    int tid = threadIdx.x;
    for (int t = tid; t < 576; t += 256) {
        int c = t / 9;
        wy[t] = __ldg(&wf[t]) * g_y[b * 64 + c];
    }
    if (tid < 64) { sa[tid] = g_a[tid]; sb[tid] = g_bc[tid]; }
    __syncthreads();
    int bx = blockIdx.x;
    int tx0 = (bx & 15) * 16, ty0 = (bx >> 4) * 16;
    int i = ty0 + (tid >> 4), j = tx0 + (tid & 15);
    const float* mb = g_m64 + (size_t)b * 64 * HW;
    float a0 = 0.f, a1 = 0.f, a2 = 0.f;
    bool interior = (tx0 > 0) && (tx0 < 240) && (ty0 > 0) && (ty0 < 240);
    if (interior) {
        const float* p0 = mb + (i - 1) * 256 + (j - 1);
        for (int c = 0; c < 64; c++) {
            float a = sa[c], bc = sb[c];
            const float* pc = p0 + (size_t)c * HW;
            const float* wt = wy + c * 9;
            float r;
            r = fmaxf(fmaf(a, __ldg(&pc[0]),   bc), 0.f); a0 = fmaf(wt[0], r, a0);
            r = fmaxf(fmaf(a, __ldg(&pc[1]),   bc), 0.f); a1 = fmaf(wt[1], r, a1);
            r = fmaxf(fmaf(a, __ldg(&pc[2]),   bc), 0.f); a2 = fmaf(wt[2], r, a2);
            r = fmaxf(fmaf(a, __ldg(&pc[256]), bc), 0.f); a0 = fmaf(wt[3], r, a0);
            r = fmaxf(fmaf(a, __ldg(&pc[257]), bc), 0.f); a1 = fmaf(wt[4], r, a1);
            r = fmaxf(fmaf(a, __ldg(&pc[258]), bc), 0.f); a2 = fmaf(wt[5], r, a2);
            r = fmaxf(fmaf(a, __ldg(&pc[512]), bc), 0.f); a0 = fmaf(wt[6], r, a0);
            r = fmaxf(fmaf(a, __ldg(&pc[513]), bc), 0.f); a1 = fmaf(wt[7], r, a1);
            r = fmaxf(fmaf(a, __ldg(&pc[514]), bc), 0.f); a2 = fmaf(wt[8], r, a2);
        }
    } else {
        for (int c = 0; c < 64; c++) {
            float a = sa[c], bc = sb[c];
            const float* mc = mb + (size_t)c * HW;
#pragma unroll
            for (int ky = 0; ky < 3; ky++) {
                int yy = i + ky - 1; if (yy < 0 || yy > 255) continue;
#pragma unroll
                for (int kx = 0; kx < 3; kx++) {
                    int xx = j + kx - 1; if (xx < 0 || xx > 255) continue;
                    float v = __ldg(&mc[yy * 256 + xx]);
                    float r = fmaxf(fmaf(a, v, bc), 0.f);
                    a0 = fmaf(wy[c * 9 + ky * 3 + kx], r, a0);
                }
            }
        }
    }
    int p = i * 256 + j;
    out[b * HW + p] = g_xp[b * HW + p] - ((a0 + a1) + a2);
}

// ---------------- launch ----------------
extern "C" void kernel_launch(void* const* d_in, const int* in_sizes, int n_in,
                              void* d_out, int out_size) {
    const float* x    = (const float*)d_in[0];
    const float* w_i3 = (const float*)d_in[1];
    const float* w_i5 = (const float*)d_in[2];
    const float* w_i7 = (const float*)d_in[3];
    const float* w_p1 = (const float*)d_in[4];
    const float* wb3  = (const float*)d_in[5];
    const float* wb5  = (const float*)d_in[6];
    const float* wb7  = (const float*)d_in[7];
    const float* wbp  = (const float*)d_in[8];
    const float* bn_g = (const float*)d_in[9];
    const float* bn_b = (const float*)d_in[10];
    const float* se1  = (const float*)d_in[11];
    const float* se2  = (const float*)d_in[12];
    const float* wf   = (const float*)d_in[13];
    float* out = (float*)d_out;

    float *xp, *h192, *m192, *m64;
    cudaGetSymbolAddress((void**)&xp,   g_xp);
    cudaGetSymbolAddress((void**)&h192, g_h192);
    cudaGetSymbolAddress((void**)&m192, g_m192);
    cudaGetSymbolAddress((void**)&m64,  g_m64);
    __half *hc, *wc3, *wc5, *wc7;
    cudaGetSymbolAddress((void**)&hc,  g_hc);
    cudaGetSymbolAddress((void**)&wc3, g_wc3);
    cudaGetSymbolAddress((void**)&wc5, g_wc5);
    cudaGetSymbolAddress((void**)&wc7, g_wc7);

    const int smem1 = (34 * 18) * 144;   // 88128
    const int smem2 = (36 * 20) * 144;   // 103680
    const int smem3 = (38 * 22) * 144;   // 120384
    const int smemP = 8 * 8704;
    cudaFuncSetAttribute(k_mconv<1>, cudaFuncAttributeMaxDynamicSharedMemorySize, smem1);
    cudaFuncSetAttribute(k_mconv<2>, cudaFuncAttributeMaxDynamicSharedMemorySize, smem2);
    cudaFuncSetAttribute(k_mconv<3>, cudaFuncAttributeMaxDynamicSharedMemorySize, smem3);
    cudaFuncSetAttribute(k_p1x1<0>, cudaFuncAttributeMaxDynamicSharedMemorySize, smemP);
    cudaFuncSetAttribute(k_p1x1<1>, cudaFuncAttributeMaxDynamicSharedMemorySize, smemP);

    // Launch order keeps k_mconv<3> at my-index 3 (ncu captures it).
    k_pre<<<512, 256>>>(x);                                                 // 0
    k_conv1f<<<dim3(64, 48), 256>>>(xp, w_i3, w_i5, w_i7, h192);            // 1
    k_p1x1<0><<<dim3(256, Bn + 1), 256, smemP>>>(h192, w_p1, nullptr, hc,
                                                 wb3, wb5, wb7,
                                                 wc3, wc5, wc7);            // 2
    dim3 gm(8, 16, Bn);
    k_mconv<3><<<gm, 256, smem3>>>(wc7, m192, 128);                         // 3 (profiled)
    k_mconv<1><<<gm, 256, smem1>>>(wc3, m192, 0);                           // 4
    k_mconv<2><<<gm, 256, smem2>>>(wc5, m192, 64);                          // 5
    k_p1x1<1><<<dim3(256, Bn), 256, smemP>>>(m192, wbp, m64, nullptr,
                                             nullptr, nullptr, nullptr,
                                             nullptr, nullptr, nullptr);    // 6
    k_bnsum<<<256, 256>>>();                                                // 7
    k_bncoef<<<1, 64>>>(bn_g, bn_b);                                        // 8
    k_ymean<<<dim3(64, 2), 256>>>();                                        // 9
    k_se<<<1, 64>>>(se1, se2);                                              // 10
    k_final<<<dim3(256, 2), 256>>>(wf, out);                                // 11
}

// round 16
// speedup vs baseline: 1.8728x; 1.3377x over previous
#include <cuda_runtime.h>
#include <cuda_bf16.h>
#include <cuda_fp16.h>
#include <math.h>

#define HW 65536
#define Bn 2

// ---------------- scratch ----------------
__device__ float g_xp[Bn * HW];
__device__ float g_h192[Bn * 192 * HW];
__device__ float g_m192[Bn * 192 * HW];
__device__ float g_m64[Bn * 64 * HW];
__device__ double g_ps1[64][4], g_ps2[64][4];
__device__ float g_a[64], g_bc[64];
__device__ double g_ym[Bn * 64];
__device__ float g_y[Bn * 64];
// channel-last fp16 input for mid convs: [b][px][64]
__device__ __half g_hc[(size_t)Bn * HW * 64];
// per-tap weights, rows [oc][64] single fp16 (permuted ic order)
__device__ __half g_wc3[9 * 64 * 64];
__device__ __half g_wc5[25 * 64 * 64];
__device__ __half g_wc7[49 * 64 * 64];

// permuted within-16 element index (k-pair interleave so LDS.64 = (k01,k89) frag regs)
__device__ __host__ __forceinline__ int permCol(int ic) {
    int jj = ic & 15, q = jj >> 1, e = jj & 1;
    int sp = (q < 4) ? 2 * q : 2 * (q - 4) + 1;
    return (ic & ~15) + 2 * sp + e;
}

// ---------------- preprocess ----------------
__device__ __forceinline__ float blendf(float v) {
    float g = fminf(fmaxf((v + 1.0f) * 0.5f, 1e-6f), 1.0f);
    return 0.6f * g + 0.4f * g * sqrtf(g);
}

__global__ void k_pre(const float* __restrict__ x) {
    int idx = blockIdx.x * blockDim.x + threadIdx.x;
    if (idx >= Bn * HW) return;
    int b = idx >> 16, p = idx & (HW - 1);
    int i = p >> 8, j = p & 255;
    const float* xb = x + b * HW;
    float c = blendf(xb[p]);
    const int   di[13] = {-2,-1,-1,-1, 0, 0, 0, 0, 0, 1, 1, 1, 2};
    const int   dj[13] = { 0,-1, 0, 1,-2,-1, 0, 1, 2,-1, 0, 1, 0};
    const float sw[13] = {0.99920032f,0.99960008f,0.99980002f,0.99960008f,
                          0.99920032f,0.99980002f,1.0f,0.99980002f,0.99920032f,
                          0.99960008f,0.99980002f,0.99960008f,0.99920032f};
    float num = 0.f, den = 0.f;
#pragma unroll
    for (int t = 0; t < 13; t++) {
        int ri = i + di[t]; ri = ri < 0 ? -ri : (ri > 255 ? 510 - ri : ri);
        int rj = j + dj[t]; rj = rj < 0 ? -rj : (rj > 255 ? 510 - rj : rj);
        float sh = blendf(xb[ri * 256 + rj]);
        float d = sh - c;
        float w = sw[t] * expf(-200.0f * d * d);
        num = fmaf(w, sh, num);
        den += w;
    }
    g_xp[idx] = num / den;
}

// ---------------- fused input convs: 1 -> 64 x three kernel sizes ----------------
template<int R>
__device__ __forceinline__ void conv1_body(
        float* tile, float* ws,
        const float* __restrict__ in, const float* __restrict__ w,
        float* __restrict__ out, int brBase, int ysub) {
    constexpr int K = 2 * R + 1, K2 = K * K;
    constexpr int TW = 32 + 2 * R;
    int bx = blockIdx.x;
    int tx0 = (bx & 7) * 32, ty0 = (bx >> 3) * 32;
    int b = ysub >> 3, ocg = ysub & 7;
    int oc0 = ocg * 8;
    int tid = threadIdx.x;            // 256
    const float* icp = in + (size_t)b * HW;
    for (int t = tid; t < TW * TW; t += 256) {
        int yy = ty0 - R + t / TW, xx = tx0 - R + t % TW;
        tile[t] = (yy >= 0 && yy < 256 && xx >= 0 && xx < 256)
                ? __ldg(&icp[yy * 256 + xx]) : 0.f;
    }
    for (int t = tid; t < 8 * K2; t += 256) {
        int o = t / K2;
        ws[t] = w[(size_t)(oc0 + o) * K2 + (t - o * K2)];
    }
    __syncthreads();
    int row = tid >> 3, xq = (tid & 7) * 4;
    float acc[8][4];
#pragma unroll
    for (int o = 0; o < 8; o++)
#pragma unroll
        for (int q = 0; q < 4; q++) acc[o][q] = 0.f;
#pragma unroll
    for (int ky = 0; ky < K; ky++) {
#pragma unroll
        for (int kx = 0; kx < K; kx++) {
            int base = (row + ky) * TW + xq + kx;
            float t0 = tile[base], t1 = tile[base + 1];
            float t2 = tile[base + 2], t3 = tile[base + 3];
#pragma unroll
            for (int o = 0; o < 8; o++) {
                float wv = ws[o * K2 + ky * K + kx];
                acc[o][0] = fmaf(t0, wv, acc[o][0]);
                acc[o][1] = fmaf(t1, wv, acc[o][1]);
                acc[o][2] = fmaf(t2, wv, acc[o][2]);
                acc[o][3] = fmaf(t3, wv, acc[o][3]);
            }
        }
    }
    size_t ob = (size_t)(b * 192 + brBase + oc0) * HW + (ty0 + row) * 256 + tx0 + xq;
#pragma unroll
    for (int o = 0; o < 8; o++)
#pragma unroll
        for (int q = 0; q < 4; q++)
            out[ob + (size_t)o * HW + q] = fmaxf(acc[o][q], 0.f);
}

// grid (64, 48): y>>4 selects branch (R=1/2/3), y&15 = b*8 + ocg.
__global__ void __launch_bounds__(256) k_conv1f(
        const float* __restrict__ xp,
        const float* __restrict__ w3, const float* __restrict__ w5,
        const float* __restrict__ w7, float* __restrict__ out) {
    __shared__ float tile[38 * 38];
    __shared__ float ws[8 * 49];
    int br = blockIdx.y >> 4;
    int ysub = blockIdx.y & 15;
    if (br == 0)      conv1_body<1>(tile, ws, xp, w3, out, 0,   ysub);
    else if (br == 1) conv1_body<2>(tile, ws, xp, w5, out, 64,  ysub);
    else              conv1_body<3>(tile, ws, xp, w7, out, 128, ysub);
}

// ---------------- mma helpers ----------------
__device__ __forceinline__ void mma_bf16(float* d, unsigned a0, unsigned a1,
                                         unsigned a2, unsigned a3,
                                         unsigned b0, unsigned b1) {
    asm("mma.sync.aligned.m16n8k16.row.col.f32.bf16.bf16.f32 "
        "{%0,%1,%2,%3},{%4,%5,%6,%7},{%8,%9},{%0,%1,%2,%3};"
        : "+f"(d[0]), "+f"(d[1]), "+f"(d[2]), "+f"(d[3])
        : "r"(a0), "r"(a1), "r"(a2), "r"(a3), "r"(b0), "r"(b1));
}
__device__ __forceinline__ void mma_f16(float* d, unsigned a0, unsigned a1,
                                        unsigned a2, unsigned a3,
                                        unsigned b0, unsigned b1) {
    asm("mma.sync.aligned.m16n8k16.row.col.f32.f16.f16.f32 "
        "{%0,%1,%2,%3},{%4,%5,%6,%7},{%8,%9},{%0,%1,%2,%3};"
        : "+f"(d[0]), "+f"(d[1]), "+f"(d[2]), "+f"(d[3])
        : "r"(a0), "r"(a1), "r"(a2), "r"(a3), "r"(b0), "r"(b1));
}

// hi/lo split + pack two values into bf16x2 words (1x1 conv staging)
__device__ __forceinline__ unsigned packhl(float a, float b, unsigned& lo) {
    __nv_bfloat16 ha = __float2bfloat16_rn(a);
    __nv_bfloat16 hb = __float2bfloat16_rn(b);
    float la = a - __bfloat162float(ha);
    float lb = b - __bfloat162float(hb);
    __nv_bfloat162 l2 = __float22bfloat162_rn(make_float2(la, lb));
    lo = *reinterpret_cast<unsigned*>(&l2);
    __nv_bfloat162 h2; h2.x = ha; h2.y = hb;
    return *reinterpret_cast<unsigned*>(&h2);
}

// ---------------- planar 1x1 conv via tensor cores: 192 -> 64 ----------------
// GEMM internals bf16 hi/lo 3-pass (rel_err ~1e-6).
// EPI 0: write channel-last fp16 SINGLE (g_hc format, 128 B/px); extra grid
//        slice (blockIdx.y == Bn) converts mid-conv weights to single fp16.
// EPI 1: planar fp32 store.
template<int EPI>
__global__ void __launch_bounds__(256) k_p1x1(
        const float* __restrict__ in, const float* __restrict__ w,
        float* __restrict__ outPlanar, __half* __restrict__ outCL,
        const float* __restrict__ wb3, const float* __restrict__ wb5,
        const float* __restrict__ wb7,
        __half* __restrict__ wc3, __half* __restrict__ wc5,
        __half* __restrict__ wc7) {
    extern __shared__ char sm[];

    // ---- weight-conversion side slice (EPI 0 only) ----
    if (EPI == 0 && blockIdx.y == Bn) {
        int gid = blockIdx.x * 256 + threadIdx.x;   // 0..65535
        for (int idx = gid; idx < 83 * 4096; idx += 65536) {
            int u = idx >> 12, r = idx & 4095;
            int oc = r >> 6, ic = r & 63;
            const float* wsrc; __half* wdst; int K2, tap;
            if (u < 9)       { wsrc = wb3; wdst = wc3; K2 = 9;  tap = u; }
            else if (u < 34) { wsrc = wb5; wdst = wc5; K2 = 25; tap = u - 9; }
            else             { wsrc = wb7; wdst = wc7; K2 = 49; tap = u - 34; }
            float v = wsrc[((size_t)oc * 64 + ic) * K2 + tap];
            __half* row = wdst + ((size_t)tap * 64 + oc) * 64;
            row[permCol(ic)] = __float2half_rn(v);
        }
        return;
    }

    char* wsmH = sm;
    char* wsmL = sm + 25600;
    char* bsmH = sm + 51200;
    char* bsmL = sm + 59520;

    int tid = threadIdx.x;
    int b = blockIdx.y;
    int px0 = blockIdx.x * 256;
    int warp = tid >> 5, lane = tid & 31;
    int lr = lane >> 2, lc = lane & 3;
    int kp = warp;
    int px8 = lane * 8;
    int pxw = warp * 32;

    const float* X = in + (size_t)b * 192 * HW + px0;

    {
        int oc = tid >> 2, seg = tid & 3;
        const float* wr = w + oc * 192 + seg * 48;
        __nv_bfloat16* dh = (__nv_bfloat16*)(wsmH + oc * 400) + seg * 48;
        __nv_bfloat16* dl = (__nv_bfloat16*)(wsmL + oc * 400) + seg * 48;
        for (int i = 0; i < 48; i++) {
            float v = __ldg(&wr[i]);
            __nv_bfloat16 h = __float2bfloat16_rn(v);
            dh[i] = h;
            dl[i] = __float2bfloat16_rn(v - __bfloat162float(h));
        }
    }
    {
        const float* r0 = X + (size_t)(2 * kp) * HW + px8;
        const float* r1 = r0 + HW;
        float4 p0 = *(const float4*)r0, p1 = *(const float4*)(r0 + 4);
        float4 p2 = *(const float4*)r1, p3 = *(const float4*)(r1 + 4);
        uint4 H0, L0, H1, L1;
        H0.x = packhl(p0.x, p2.x, L0.x); H0.y = packhl(p0.y, p2.y, L0.y);
        H0.z = packhl(p0.z, p2.z, L0.z); H0.w = packhl(p0.w, p2.w, L0.w);
        H1.x = packhl(p1.x, p3.x, L1.x); H1.y = packhl(p1.y, p3.y, L1.y);
        H1.z = packhl(p1.z, p3.z, L1.z); H1.w = packhl(p1.w, p3.w, L1.w);
        *(uint4*)(bsmH + kp * 1040 + lane * 32) = H0;
        *(uint4*)(bsmH + kp * 1040 + lane * 32 + 16) = H1;
        *(uint4*)(bsmL + kp * 1040 + lane * 32) = L0;
        *(uint4*)(bsmL + kp * 1040 + lane * 32 + 16) = L1;
    }
    __syncthreads();

    float d[4][4][4];
#pragma unroll
    for (int mf = 0; mf < 4; mf++)
#pragma unroll
        for (int nf = 0; nf < 4; nf++)
#pragma unroll
            for (int q = 0; q < 4; q++) d[mf][nf][q] = 0.f;

    for (int c = 0; c < 12; c++) {
        float4 p0, p1, p2, p3;
        bool more = (c < 11);
        if (more) {
            const float* r0 = X + (size_t)((c + 1) * 16 + 2 * kp) * HW + px8;
            const float* r1 = r0 + HW;
            p0 = *(const float4*)r0; p1 = *(const float4*)(r0 + 4);
            p2 = *(const float4*)r1; p3 = *(const float4*)(r1 + 4);
        }
        unsigned BH0[4], BH1[4], BL0[4], BL1[4];
#pragma unroll
        for (int nf = 0; nf < 4; nf++) {
            int col = (pxw + nf * 8 + lr) * 4;
            const char* ph = bsmH + lc * 1040 + col;
            const char* pl = bsmL + lc * 1040 + col;
            BH0[nf] = *(const unsigned*)ph;
            BH1[nf] = *(const unsigned*)(ph + 4 * 1040);
            BL0[nf] = *(const unsigned*)pl;
            BL1[nf] = *(const unsigned*)(pl + 4 * 1040);
        }
#pragma unroll
        for (int mf = 0; mf < 4; mf++) {
            const char* ah = wsmH + (mf * 16 + lr) * 400 + c * 32 + lc * 4;
            const char* al = wsmL + (mf * 16 + lr) * 400 + c * 32 + lc * 4;
            unsigned AH0 = *(const unsigned*)ah;
            unsigned AH1 = *(const unsigned*)(ah + 8 * 400);
            unsigned AH2 = *(const unsigned*)(ah + 16);
            unsigned AH3 = *(const unsigned*)(ah + 8 * 400 + 16);
            unsigned AL0 = *(const unsigned*)al;
            unsigned AL1 = *(const unsigned*)(al + 8 * 400);
            unsigned AL2 = *(const unsigned*)(al + 16);
            unsigned AL3 = *(const unsigned*)(al + 8 * 400 + 16);
#pragma unroll
            for (int nf = 0; nf < 4; nf++) {
                mma_bf16(d[mf][nf], AH0, AH1, AH2, AH3, BH0[nf], BH1[nf]);
                mma_bf16(d[mf][nf], AH0, AH1, AH2, AH3, BL0[nf], BL1[nf]);
                mma_bf16(d[mf][nf], AL0, AL1, AL2, AL3, BH0[nf], BH1[nf]);
            }
        }
        __syncthreads();
        if (more) {
            uint4 H0, L0, H1, L1;
            H0.x = packhl(p0.x, p2.x, L0.x); H0.y = packhl(p0.y, p2.y, L0.y);
            H0.z = packhl(p0.z, p2.z, L0.z); H0.w = packhl(p0.w, p2.w, L0.w);
            H1.x = packhl(p1.x, p3.x, L1.x); H1.y = packhl(p1.y, p3.y, L1.y);
            H1.z = packhl(p1.z, p3.z, L1.z); H1.w = packhl(p1.w, p3.w, L1.w);
            *(uint4*)(bsmH + kp * 1040 + lane * 32) = H0;
            *(uint4*)(bsmH + kp * 1040 + lane * 32 + 16) = H1;
            *(uint4*)(bsmL + kp * 1040 + lane * 32) = L0;
            *(uint4*)(bsmL + kp * 1040 + lane * 32 + 16) = L1;
        }
        __syncthreads();
    }

    if (EPI == 1) {
#pragma unroll
        for (int mf = 0; mf < 4; mf++) {
            int oc = mf * 16 + lr;
#pragma unroll
            for (int nf = 0; nf < 4; nf++) {
                int px = px0 + pxw + nf * 8 + 2 * lc;
                *(float2*)&outPlanar[(size_t)(b * 64 + oc) * HW + px] =
                    make_float2(d[mf][nf][0], d[mf][nf][1]);
                *(float2*)&outPlanar[(size_t)(b * 64 + oc + 8) * HW + px] =
                    make_float2(d[mf][nf][2], d[mf][nf][3]);
            }
        }
    } else {
        // channel-last fp16 single via smem staging (g_hc format, permCol)
        char* est = sm + warp * 4608;   // [32 px][144 B rows, 16B-aligned]
#pragma unroll
        for (int mf = 0; mf < 4; mf++) {
            int col0 = permCol(mf * 16 + lr);
            int col8 = permCol(mf * 16 + lr + 8);
#pragma unroll
            for (int nf = 0; nf < 4; nf++) {
                int pxl = nf * 8 + 2 * lc;
#pragma unroll
                for (int e = 0; e < 2; e++) {
                    *(__half*)(est + (pxl + e) * 144 + col0 * 2) =
                        __float2half_rn(d[mf][nf][e]);
                    *(__half*)(est + (pxl + e) * 144 + col8 * 2) =
                        __float2half_rn(d[mf][nf][2 + e]);
                }
            }
        }
        __syncthreads();
#pragma unroll
        for (int r = 0; r < 8; r++) {
            int pxl = r * 4 + (lane >> 3);
            int ch = (lane & 7) * 16;
            uint4 v = *(const uint4*)(sm + warp * 4608 + pxl * 144 + ch);
            *(uint4*)((char*)outCL + ((size_t)b * HW + px0 + pxw + pxl) * 128 + ch) = v;
        }
    }
}

// ---------------- mid conv: 64->64, KxK, fp16 SINGLE-pass ------
// Warp tile M=64px x N=64oc; CTA 256 thr, output tile 32x16; barrier-free taps.
// Weights single fp16 [tap][oc][64] (128 B rows), streamed via __ldg (L1-hot).
template<int R>
__global__ void __launch_bounds__(256) k_mconv(
        const __half* __restrict__ wc,
        float* __restrict__ out, int brBase) {
    constexpr int K = 2 * R + 1, K2 = K * K;
    constexpr int TWX = 32 + 2 * R, TWY = 16 + 2 * R, ROWS = TWX * TWY;
    constexpr int RB = 144;             // 64 fp16 = 128 B data + 16 B pad
    extern __shared__ char smem[];
    char* tile = smem;

    int tid = threadIdx.x;
    int b = blockIdx.z;
    int x0 = blockIdx.x * 32, y0 = blockIdx.y * 16;
    int warp = tid >> 5, lane = tid & 31;
    int lr = lane >> 2, lc = lane & 3;

    {
        const __half* src = g_hc + (size_t)b * HW * 64;
        for (int t = tid; t < ROWS * 8; t += 256) {
            int row = t >> 3, chunk = t & 7;
            int gy = y0 - R + row / TWX;
            int gx = x0 - R + row % TWX;
            uint4 v = make_uint4(0u, 0u, 0u, 0u);
            if (gy >= 0 && gy < 256 && gx >= 0 && gx < 256)
                v = *(const uint4*)(src + ((size_t)gy * 256 + gx) * 64 + chunk * 8);
            *(uint4*)(tile + row * RB + chunk * 16) = v;
        }
    }
    __syncthreads();   // only barrier

    float d[4][8][4];
#pragma unroll
    for (int f = 0; f < 4; f++)
#pragma unroll
        for (int n = 0; n < 8; n++)
#pragma unroll
            for (int q = 0; q < 4; q++) d[f][n][q] = 0.f;

    for (int tap = 0; tap < K2; tap++) {
        int ky = tap / K, kx = tap % K;
        const char* wt = (const char*)(wc + (size_t)tap * 4096) + lr * 128 + lc * 8;
        int abase[4];
#pragma unroll
        for (int f = 0; f < 4; f++)
            abase[f] = (((warp * 2 + (f >> 1) + ky) * TWX) + ((f & 1) * 16) + lr + kx) * RB + lc * 8;

#pragma unroll
        for (int c = 0; c < 4; c++) {
            int co = c * 32;
            uint2 B[8];
#pragma unroll
            for (int n = 0; n < 8; n++)
                B[n] = __ldg((const uint2*)(wt + n * 8 * 128 + co));
#pragma unroll
            for (int f = 0; f < 4; f++) {
                const char* p = tile + abase[f] + co;
                uint2 A0 = *(const uint2*)p;
                uint2 A1 = *(const uint2*)(p + 8 * RB);
#pragma unroll
                for (int n = 0; n < 8; n++)
                    mma_f16(d[f][n], A0.x, A1.x, A0.y, A1.y, B[n].x, B[n].y);
            }
        }
    }

#pragma unroll
    for (int f = 0; f < 4; f++) {
        int y = y0 + warp * 2 + (f >> 1);
        int x = x0 + (f & 1) * 16 + lr;
#pragma unroll
        for (int n = 0; n < 8; n++) {
            int oc = n * 8 + lc * 2;
            float* o0 = out + ((size_t)(b * 192 + brBase + oc) * HW + y * 256 + x);
            o0[0]       = fmaxf(d[f][n][0], 0.f);
            o0[8]       = fmaxf(d[f][n][2], 0.f);
            o0[HW]      = fmaxf(d[f][n][1], 0.f);
            o0[HW + 8]  = fmaxf(d[f][n][3], 0.f);
        }
    }
}

// ---------------- BN stats ----------------
__global__ void k_bnsum() {
    int c = blockIdx.x >> 2, seg = blockIdx.x & 3, tid = threadIdx.x;
    int base = seg * 32768;
    double s[4] = {0, 0, 0, 0}, s2[4] = {0, 0, 0, 0};
    for (int u = 0; u < 32; u++) {
        int t = base + u * 1024 + tid * 4;
#pragma unroll
        for (int q = 0; q < 4; q++) {
            int tt = t + q;
            int bb = tt >> 16, p = tt & (HW - 1);
            float v = g_m64[(size_t)(bb * 64 + c) * HW + p];
            s[q] += v; s2[q] += (double)v * v;
        }
    }
    double ss = (s[0] + s[1]) + (s[2] + s[3]);
    double ss2 = (s2[0] + s2[1]) + (s2[2] + s2[3]);
    __shared__ double sh1[256], sh2[256];
    sh1[tid] = ss; sh2[tid] = ss2; __syncthreads();
    for (int st = 128; st > 0; st >>= 1) {
        if (tid < st) { sh1[tid] += sh1[tid + st]; sh2[tid] += sh2[tid + st]; }
        __syncthreads();
    }
    if (tid == 0) { g_ps1[c][seg] = sh1[0]; g_ps2[c][seg] = sh2[0]; }
}

__global__ void k_bncoef(const float* __restrict__ bn_g, const float* __restrict__ bn_b) {
    int c = threadIdx.x;
    double N = (double)(Bn * HW);
    double s1 = (g_ps1[c][0] + g_ps1[c][1]) + (g_ps1[c][2] + g_ps1[c][3]);
    double s2 = (g_ps2[c][0] + g_ps2[c][1]) + (g_ps2[c][2] + g_ps2[c][3]);
    double mean = s1 / N;
    double var = s2 / N - mean * mean;
    float a = (float)((double)bn_g[c] / sqrt(var + 1e-5));
    g_a[c] = a;
    g_bc[c] = bn_b[c] - (float)mean * a;
}

__global__ void k_ymean() {
    int c = blockIdx.x, b = blockIdx.y, tid = threadIdx.x;
    float a = g_a[c], bc = g_bc[c];
    const float* mp = g_m64 + (size_t)(b * 64 + c) * HW;
    double s[4] = {0, 0, 0, 0};
    for (int p = tid * 4; p < HW; p += 1024) {
#pragma unroll
        for (int q = 0; q < 4; q++)
            s[q] += (double)fmaxf(fmaf(a, mp[p + q], bc), 0.f);
    }
    __shared__ double sh[256];
    sh[tid] = (s[0] + s[1]) + (s[2] + s[3]); __syncthreads();
    for (int st = 128; st > 0; st >>= 1) {
        if (tid < st) sh[tid] += sh[tid + st];
        __syncthreads();
    }
    if (tid == 0) g_ym[b * 64 + c] = sh[0] / (double)HW;
}

__global__ void k_se(const float* __restrict__ se1, const float* __restrict__ se2) {
    __shared__ float t1[2][4];
    int tid = threadIdx.x;
    for (int b = 0; b < 2; b++) {
        if (tid < 4) {
            float s = 0.f;
            for (int c = 0; c < 64; c++) s += se1[tid * 64 + c] * (float)g_ym[b * 64 + c];
            t1[b][tid] = fmaxf(s, 0.f);
        }
    }
    __syncthreads();
    for (int b = 0; b < 2; b++) {
        float z = 0.f;
        for (int j = 0; j < 4; j++) z += se2[tid * 4 + j] * t1[b][j];
        g_y[b * 64 + tid] = 1.f / (1.f + expf(-z));
    }
}

// ---------------- final: interior fast path + 3 accumulators ----------------
__global__ void k_final(const float* __restrict__ wf, float* __restrict__ out) {
    __shared__ float wy[576], sa[64], sb[64];
    int b = blockIdx.y;
    int tid = threadIdx.x;
    for (int t = tid; t < 576; t += 256) {
        int c = t / 9;
        wy[t] = __ldg(&wf[t]) * g_y[b * 64 + c];
    }
    if (tid < 64) { sa[tid] = g_a[tid]; sb[tid] = g_bc[tid]; }
    __syncthreads();
    int bx = blockIdx.x;
    int tx0 = (bx & 15) * 16, ty0 = (bx >> 4) * 16;
    int i = ty0 + (tid >> 4), j = tx0 + (tid & 15);
    const float* mb = g_m64 + (size_t)b * 64 * HW;
    float a0 = 0.f, a1 = 0.f, a2 = 0.f;
    bool interior = (tx0 > 0) && (tx0 < 240) && (ty0 > 0) && (ty0 < 240);
    if (interior) {
        const float* p0 = mb + (i - 1) * 256 + (j - 1);
        for (int c = 0; c < 64; c++) {
            float a = sa[c], bc = sb[c];
            const float* pc = p0 + (size_t)c * HW;
            const float* wt = wy + c * 9;
            float r;
            r = fmaxf(fmaf(a, __ldg(&pc[0]),   bc), 0.f); a0 = fmaf(wt[0], r, a0);
            r = fmaxf(fmaf(a, __ldg(&pc[1]),   bc), 0.f); a1 = fmaf(wt[1], r, a1);
            r = fmaxf(fmaf(a, __ldg(&pc[2]),   bc), 0.f); a2 = fmaf(wt[2], r, a2);
            r = fmaxf(fmaf(a, __ldg(&pc[256]), bc), 0.f); a0 = fmaf(wt[3], r, a0);
            r = fmaxf(fmaf(a, __ldg(&pc[257]), bc), 0.f); a1 = fmaf(wt[4], r, a1);
            r = fmaxf(fmaf(a, __ldg(&pc[258]), bc), 0.f); a2 = fmaf(wt[5], r, a2);
            r = fmaxf(fmaf(a, __ldg(&pc[512]), bc), 0.f); a0 = fmaf(wt[6], r, a0);
            r = fmaxf(fmaf(a, __ldg(&pc[513]), bc), 0.f); a1 = fmaf(wt[7], r, a1);
            r = fmaxf(fmaf(a, __ldg(&pc[514]), bc), 0.f); a2 = fmaf(wt[8], r, a2);
        }
    } else {
        for (int c = 0; c < 64; c++) {
            float a = sa[c], bc = sb[c];
            const float* mc = mb + (size_t)c * HW;
#pragma unroll
            for (int ky = 0; ky < 3; ky++) {
                int yy = i + ky - 1; if (yy < 0 || yy > 255) continue;
#pragma unroll
                for (int kx = 0; kx < 3; kx++) {
                    int xx = j + kx - 1; if (xx < 0 || xx > 255) continue;
                    float v = __ldg(&mc[yy * 256 + xx]);
                    float r = fmaxf(fmaf(a, v, bc), 0.f);
                    a0 = fmaf(wy[c * 9 + ky * 3 + kx], r, a0);
                }
            }
        }
    }
    int p = i * 256 + j;
    out[b * HW + p] = g_xp[b * HW + p] - ((a0 + a1) + a2);
}

// ---------------- launch ----------------
extern "C" void kernel_launch(void* const* d_in, const int* in_sizes, int n_in,
                              void* d_out, int out_size) {
    const float* x    = (const float*)d_in[0];
    const float* w_i3 = (const float*)d_in[1];
    const float* w_i5 = (const float*)d_in[2];
    const float* w_i7 = (const float*)d_in[3];
    const float* w_p1 = (const float*)d_in[4];
    const float* wb3  = (const float*)d_in[5];
    const float* wb5  = (const float*)d_in[6];
    const float* wb7  = (const float*)d_in[7];
    const float* wbp  = (const float*)d_in[8];
    const float* bn_g = (const float*)d_in[9];
    const float* bn_b = (const float*)d_in[10];
    const float* se1  = (const float*)d_in[11];
    const float* se2  = (const float*)d_in[12];
    const float* wf   = (const float*)d_in[13];
    float* out = (float*)d_out;

    float *xp, *h192, *m192, *m64;
    cudaGetSymbolAddress((void**)&xp,   g_xp);
    cudaGetSymbolAddress((void**)&h192, g_h192);
    cudaGetSymbolAddress((void**)&m192, g_m192);
    cudaGetSymbolAddress((void**)&m64,  g_m64);
    __half *hc, *wc3, *wc5, *wc7;
    cudaGetSymbolAddress((void**)&hc,  g_hc);
    cudaGetSymbolAddress((void**)&wc3, g_wc3);
    cudaGetSymbolAddress((void**)&wc5, g_wc5);
    cudaGetSymbolAddress((void**)&wc7, g_wc7);

    const int smem1 = (34 * 18) * 144;   // 88128
    const int smem2 = (36 * 20) * 144;   // 103680
    const int smem3 = (38 * 22) * 144;   // 120384
    const int smemP = 8 * 8704;
    cudaFuncSetAttribute(k_mconv<1>, cudaFuncAttributeMaxDynamicSharedMemorySize, smem1);
    cudaFuncSetAttribute(k_mconv<2>, cudaFuncAttributeMaxDynamicSharedMemorySize, smem2);
    cudaFuncSetAttribute(k_mconv<3>, cudaFuncAttributeMaxDynamicSharedMemorySize, smem3);
    cudaFuncSetAttribute(k_p1x1<0>, cudaFuncAttributeMaxDynamicSharedMemorySize, smemP);
    cudaFuncSetAttribute(k_p1x1<1>, cudaFuncAttributeMaxDynamicSharedMemorySize, smemP);

    // Launch order keeps k_mconv<3> at my-index 3 (ncu captures it).
    k_pre<<<512, 256>>>(x);                                                 // 0
    k_conv1f<<<dim3(64, 48), 256>>>(xp, w_i3, w_i5, w_i7, h192);            // 1
    k_p1x1<0><<<dim3(256, Bn + 1), 256, smemP>>>(h192, w_p1, nullptr, hc,
                                                 wb3, wb5, wb7,
                                                 wc3, wc5, wc7);            // 2
    dim3 gm(8, 16, Bn);
    k_mconv<3><<<gm, 256, smem3>>>(wc7, m192, 128);                         // 3 (profiled)
    k_mconv<1><<<gm, 256, smem1>>>(wc3, m192, 0);                           // 4
    k_mconv<2><<<gm, 256, smem2>>>(wc5, m192, 64);                          // 5
    k_p1x1<1><<<dim3(256, Bn), 256, smemP>>>(m192, wbp, m64, nullptr,
                                             nullptr, nullptr, nullptr,
                                             nullptr, nullptr, nullptr);    // 6
    k_bnsum<<<256, 256>>>();                                                // 7
    k_bncoef<<<1, 64>>>(bn_g, bn_b);                                        // 8
    k_ymean<<<dim3(64, 2), 256>>>();                                        // 9
    k_se<<<1, 64>>>(se1, se2);                                              // 10
    k_final<<<dim3(256, 2), 256>>>(wf, out);                                // 11
}